// round 8
// baseline (speedup 1.0000x reference)
#include <cuda_runtime.h>
#include <stdint.h>
#include <math.h>

#define TT 2048
#define BB 2
#define DD 512
#define HH 8
#define DH 64
#define MAXREL 32
#define SCALE_L2E 0.1803368801111244f   // (DH^-0.5) * log2(e)
#define L2E 1.4426950408889634f
#define KCH 32
#define NCH (TT / KCH)                  // 64 chunks

// Scratch (allocation-free rule: __device__ globals)
__device__ float g_Q[BB * TT * DD];
__device__ float g_K[BB * TT * DD];
__device__ float g_V[BB * TT * DD];
__device__ float g_AO[BB * TT * DD];
__device__ float g_Xr[BB * TT * DD];        // tf32-rounded hidden states
__device__ float g_Wr[4 * DD * DD];         // tf32-rounded Wq,Wk,Wv,Wo

// ---------------------------------------------------------------------------
// helpers
// ---------------------------------------------------------------------------
__device__ __forceinline__ uint32_t f2tf32(float f) {
    uint32_t r;
    asm("cvt.rna.tf32.f32 %0, %1;" : "=r"(r) : "f"(f));
    return r;
}
__device__ __forceinline__ float tf32r(float f) { return __uint_as_float(f2tf32(f)); }
__device__ __forceinline__ float ex2(float x) {
    float r;
    asm("ex2.approx.ftz.f32 %0, %1;" : "=f"(r) : "f"(x));
    return r;
}
__device__ __forceinline__ void mma8(float* d, const uint32_t* a, uint32_t b0, uint32_t b1) {
    asm volatile(
        "mma.sync.aligned.m16n8k8.row.col.f32.tf32.tf32.f32 "
        "{%0,%1,%2,%3}, {%4,%5,%6,%7}, {%8,%9}, {%0,%1,%2,%3};"
        : "+f"(d[0]), "+f"(d[1]), "+f"(d[2]), "+f"(d[3])
        : "r"(a[0]), "r"(a[1]), "r"(a[2]), "r"(a[3]), "r"(b0), "r"(b1));
}
__device__ __forceinline__ uint32_t fbits(float f) { return __float_as_uint(f); }
__device__ __forceinline__ uint32_t smem_u32(const void* p) {
    uint32_t a;
    asm("{ .reg .u64 t; cvta.to.shared.u64 t, %1; cvt.u32.u64 %0, t; }" : "=r"(a) : "l"(p));
    return a;
}
__device__ __forceinline__ void cpasync16(uint32_t dst, const void* src) {
    asm volatile("cp.async.cg.shared.global [%0], [%1], 16;" :: "r"(dst), "l"(src));
}
#define CP_COMMIT() asm volatile("cp.async.commit_group;" ::: "memory")
#define CP_WAIT1()  asm volatile("cp.async.wait_group 1;" ::: "memory")

// ---------------------------------------------------------------------------
// Elementwise tf32 rounding pass
// ---------------------------------------------------------------------------
__global__ void round_kernel(const float4* __restrict__ src, float4* __restrict__ dst, int n4)
{
    int i = blockIdx.x * blockDim.x + threadIdx.x;
    if (i < n4) {
        float4 v = src[i];
        v.x = tf32r(v.x); v.y = tf32r(v.y); v.z = tf32r(v.z); v.w = tf32r(v.w);
        dst[i] = v;
    }
}

// ---------------------------------------------------------------------------
// GEMM: C[M,N] = X[M,K] @ W[K,N] + bias[N]. Inputs pre-rounded to tf32.
// BM=64, BN=64, BK=32, 128 threads (4 warps, m16n64). 2-stage cp.async.
// ---------------------------------------------------------------------------
#define XPAD 36
#define WPAD 72
#define GXS_F (64 * XPAD)          // 2304
#define GWS_F (32 * WPAD)          // 2304
#define GSTG_F (GXS_F + GWS_F)     // 4608
#define NKCH 16

__global__ void __launch_bounds__(128) gemm_tf32_kernel(
    const float* __restrict__ X, const float* __restrict__ W,
    const float* __restrict__ bias, float* __restrict__ C,
    int round_out)
{
    __shared__ __align__(16) float sm[2 * GSTG_F];
    __shared__ float bs[64];
    const uint32_t smb = smem_u32(sm);
    const int N = DD, K = DD;

    const int tid = threadIdx.x;
    const int lane = tid & 31;
    const int wid = tid >> 5;
    const int wr = wid * 16;
    const int g = lane >> 2, q4 = lane & 3;
    const int m0 = blockIdx.y * 64;
    const int n0 = blockIdx.x * 64;

    const int xr = tid >> 3, xc = (tid & 7) * 4;     // X: row 0..15(+16..), col
    const int wrr = tid >> 4, wc = (tid & 15) * 4;   // W: row 0..7(+8..), col

    // prologue: stage 0
    {
        const uint32_t xd = smb;
        const uint32_t wd = smb + GXS_F * 4;
#pragma unroll
        for (int it = 0; it < 4; it++)
            cpasync16(xd + ((xr + it * 16) * XPAD + xc) * 4,
                      &X[(size_t)(m0 + xr + it * 16) * K + xc]);
#pragma unroll
        for (int it = 0; it < 4; it++)
            cpasync16(wd + ((wrr + it * 8) * WPAD + wc) * 4,
                      &W[(size_t)(wrr + it * 8) * N + n0 + wc]);
    }
    CP_COMMIT();
    if (tid < 64) bs[tid] = bias[n0 + tid];

    float c[8][4];
#pragma unroll
    for (int nt = 0; nt < 8; nt++)
#pragma unroll
        for (int j = 0; j < 4; j++) c[nt][j] = 0.0f;

    for (int ch = 0; ch < NKCH; ch++) {
        // issue next stage (or empty commit to keep group count in step)
        if (ch + 1 < NKCH) {
            const int k0 = (ch + 1) * 32;
            const int st = (ch + 1) & 1;
            const uint32_t xd = smb + (st * GSTG_F) * 4;
            const uint32_t wd = smb + (st * GSTG_F + GXS_F) * 4;
#pragma unroll
            for (int it = 0; it < 4; it++)
                cpasync16(xd + ((xr + it * 16) * XPAD + xc) * 4,
                          &X[(size_t)(m0 + xr + it * 16) * K + k0 + xc]);
#pragma unroll
            for (int it = 0; it < 4; it++)
                cpasync16(wd + ((k0 + wrr + it * 8) * 0 + (wrr + it * 8) * WPAD + wc) * 4,
                          &W[(size_t)(k0 + wrr + it * 8) * N + n0 + wc]);
        }
        CP_COMMIT();
        CP_WAIT1();
        __syncthreads();

        const float* Xs = sm + (ch & 1) * GSTG_F;
        const float* Ws = Xs + GXS_F;

#pragma unroll
        for (int ks = 0; ks < 4; ks++) {
            uint32_t a[4];
            const int ac = q4 + ks * 8;
            a[0] = fbits(Xs[(wr + g) * XPAD + ac]);
            a[1] = fbits(Xs[(wr + g + 8) * XPAD + ac]);
            a[2] = fbits(Xs[(wr + g) * XPAD + ac + 4]);
            a[3] = fbits(Xs[(wr + g + 8) * XPAD + ac + 4]);
#pragma unroll
            for (int nt = 0; nt < 8; nt++) {
                uint32_t b0 = fbits(Ws[(ks * 8 + q4) * WPAD + nt * 8 + g]);
                uint32_t b1 = fbits(Ws[(ks * 8 + q4 + 4) * WPAD + nt * 8 + g]);
                mma8(c[nt], a, b0, b1);
            }
        }
        __syncthreads();   // mma reads done before this buffer is refilled
    }

    const int r0 = m0 + wr + g;
#pragma unroll
    for (int nt = 0; nt < 8; nt++) {
        int col = nt * 8 + q4 * 2;
        float o00 = c[nt][0] + bs[col], o01 = c[nt][1] + bs[col + 1];
        float o10 = c[nt][2] + bs[col], o11 = c[nt][3] + bs[col + 1];
        if (round_out) {
            o00 = tf32r(o00); o01 = tf32r(o01); o10 = tf32r(o10); o11 = tf32r(o11);
        }
        *(float2*)&C[(size_t)r0 * N + n0 + col] = make_float2(o00, o01);
        *(float2*)&C[(size_t)(r0 + 8) * N + n0 + col] = make_float2(o10, o11);
    }
}

// ---------------------------------------------------------------------------
// Attention. Grid (T/64, H, B) = 512 CTAs, 128 threads (4 warps, m16n64).
// Q fragments in registers; K/V streamed in 32-key chunks, 3-stage cp.async;
// register P via shuffles; no max-subtraction softmax.
// ---------------------------------------------------------------------------
#define KPADA 68
#define VPADA 72
#define AKS_F (KCH * KPADA)         // 2176
#define AVS_F (KCH * VPADA)         // 2304
#define ASTG_F (AKS_F + AVS_F)      // 4480

__global__ void __launch_bounds__(128) attn_mma_kernel(
    const float* __restrict__ Q, const float* __restrict__ K,
    const float* __restrict__ V, const float* __restrict__ rb,
    float* __restrict__ O)
{
    __shared__ __align__(16) float sm[3 * ASTG_F];
    __shared__ float bias_s[72];
    const uint32_t smb = smem_u32(sm);

    const int tid = threadIdx.x;
    const int lane = tid & 31;
    const int wid = tid >> 5;        // 0..3
    const int wr = wid * 16;
    const int g = lane >> 2, q4 = lane & 3;
    const int q0 = blockIdx.x * 64;
    const int h = blockIdx.y, b = blockIdx.z;
    const int base = b * TT * DD + h * DH;

    const int cr = tid >> 4;             // 0..7 (chunk row group)
    const int cc = (tid & 15) * 4;       // col

    // prologue: stages 0 and 1
#pragma unroll
    for (int st = 0; st < 2; st++) {
        const int k0 = st * KCH;
        const uint32_t kd = smb + (st * ASTG_F) * 4;
        const uint32_t vd = smb + (st * ASTG_F + AKS_F) * 4;
#pragma unroll
        for (int it = 0; it < 4; it++) {
            int r = cr + it * 8;
            cpasync16(kd + (r * KPADA + cc) * 4, &K[base + (k0 + r) * DD + cc]);
            cpasync16(vd + (r * VPADA + cc) * 4, &V[base + (k0 + r) * DD + cc]);
        }
        CP_COMMIT();
    }

    if (tid < 2 * MAXREL + 1) bias_s[tid] = rb[h * (2 * MAXREL + 1) + tid] * L2E;
    const float blo = rb[h * (2 * MAXREL + 1)] * L2E;
    const float bhi = rb[h * (2 * MAXREL + 1) + 2 * MAXREL] * L2E;

    // Q fragments in registers (rows wr+g, wr+g+8; pre-rounded in GMEM)
    uint32_t qf[8][4];
#pragma unroll
    for (int ks = 0; ks < 8; ks++) {
        const int ac = q4 + ks * 8;
        qf[ks][0] = fbits(__ldg(&Q[base + (q0 + wr + g) * DD + ac]));
        qf[ks][1] = fbits(__ldg(&Q[base + (q0 + wr + g + 8) * DD + ac]));
        qf[ks][2] = fbits(__ldg(&Q[base + (q0 + wr + g) * DD + ac + 4]));
        qf[ks][3] = fbits(__ldg(&Q[base + (q0 + wr + g + 8) * DD + ac + 4]));
    }

    float o[8][4];
#pragma unroll
    for (int nt = 0; nt < 8; nt++)
#pragma unroll
        for (int j = 0; j < 4; j++) o[nt][j] = 0.0f;
    float ls0 = 0.0f, ls1 = 0.0f;

    const int dr0 = q0 + wr + g;
    const int src0 = g * 4 + (q4 >> 1);
    const int src1 = src0 + 2;
    const bool oddq = (q4 & 1);

    for (int ch = 0; ch < NCH; ch++) {
        const int k0 = ch * KCH;
        CP_WAIT1();
        __syncthreads();

        // issue chunk ch+2 (empty commit in tail keeps group accounting uniform)
        if (ch + 2 < NCH) {
            const int kn = (ch + 2) * KCH;
            const int st = (ch + 2) % 3;
            const uint32_t kd = smb + (st * ASTG_F) * 4;
            const uint32_t vd = smb + (st * ASTG_F + AKS_F) * 4;
#pragma unroll
            for (int it = 0; it < 4; it++) {
                int r = cr + it * 8;
                cpasync16(kd + (r * KPADA + cc) * 4, &K[base + (kn + r) * DD + cc]);
                cpasync16(vd + (r * VPADA + cc) * 4, &V[base + (kn + r) * DD + cc]);
            }
        }
        CP_COMMIT();

        const float* Ks = sm + (ch % 3) * ASTG_F;
        const float* Vs = Ks + AKS_F;

        // S = Q K^T  (m=16 rows per warp; n=32 keys; k=64 d)
        float s[4][4];
#pragma unroll
        for (int nt = 0; nt < 4; nt++)
#pragma unroll
            for (int j = 0; j < 4; j++) s[nt][j] = 0.0f;

#pragma unroll
        for (int ks = 0; ks < 8; ks++) {
            const int bc = q4 + ks * 8;
#pragma unroll
            for (int nt = 0; nt < 4; nt++) {
                uint32_t b0 = fbits(Ks[(nt * 8 + g) * KPADA + bc]);
                uint32_t b1 = fbits(Ks[(nt * 8 + g) * KPADA + bc + 4]);
                mma8(s[nt], qf[ks], b0, b1);
            }
        }

        // softmax weights
        const int dmin = q0 - (k0 + KCH - 1);
        const int dmax = q0 + 63 - k0;
        if (dmin >= MAXREL) {
#pragma unroll
            for (int nt = 0; nt < 4; nt++)
#pragma unroll
                for (int j = 0; j < 4; j++) s[nt][j] = ex2(fmaf(s[nt][j], SCALE_L2E, bhi));
        } else if (dmax <= -MAXREL) {
#pragma unroll
            for (int nt = 0; nt < 4; nt++)
#pragma unroll
                for (int j = 0; j < 4; j++) s[nt][j] = ex2(fmaf(s[nt][j], SCALE_L2E, blo));
        } else {
#pragma unroll
            for (int nt = 0; nt < 4; nt++) {
                const int c0 = k0 + nt * 8 + q4 * 2;
#pragma unroll
                for (int j = 0; j < 4; j++) {
                    int rel = (dr0 + ((j >> 1) << 3)) - (c0 + (j & 1));
                    rel = min(max(rel, -MAXREL), MAXREL) + MAXREL;
                    s[nt][j] = ex2(fmaf(s[nt][j], SCALE_L2E, bias_s[rel]));
                }
            }
        }
#pragma unroll
        for (int nt = 0; nt < 4; nt++) {
            ls0 += s[nt][0] + s[nt][1];
            ls1 += s[nt][2] + s[nt][3];
            s[nt][0] = tf32r(s[nt][0]);
            s[nt][1] = tf32r(s[nt][1]);
            s[nt][2] = tf32r(s[nt][2]);
            s[nt][3] = tf32r(s[nt][3]);
        }

        // O += P V: P A-fragments from S C-fragments via shuffles (4 k-steps)
#pragma unroll
        for (int ks = 0; ks < 4; ks++) {
            float v0 = __shfl_sync(0xffffffffu, s[ks][0], src0);
            float v1 = __shfl_sync(0xffffffffu, s[ks][1], src0);
            float v2 = __shfl_sync(0xffffffffu, s[ks][2], src0);
            float v3 = __shfl_sync(0xffffffffu, s[ks][3], src0);
            float w0 = __shfl_sync(0xffffffffu, s[ks][0], src1);
            float w1 = __shfl_sync(0xffffffffu, s[ks][1], src1);
            float w2 = __shfl_sync(0xffffffffu, s[ks][2], src1);
            float w3 = __shfl_sync(0xffffffffu, s[ks][3], src1);
            uint32_t a[4];
            a[0] = fbits(oddq ? v1 : v0);
            a[1] = fbits(oddq ? v3 : v2);
            a[2] = fbits(oddq ? w1 : w0);
            a[3] = fbits(oddq ? w3 : w2);
#pragma unroll
            for (int nt = 0; nt < 8; nt++) {
                uint32_t b0 = fbits(Vs[(ks * 8 + q4) * VPADA + nt * 8 + g]);
                uint32_t b1 = fbits(Vs[(ks * 8 + q4 + 4) * VPADA + nt * 8 + g]);
                mma8(o[nt], a, b0, b1);
            }
        }
        __syncthreads();   // all warps done with this buffer before refill
    }

    // reduce row sums across the 4 lanes of each quad
    ls0 += __shfl_xor_sync(0xffffffffu, ls0, 1);
    ls0 += __shfl_xor_sync(0xffffffffu, ls0, 2);
    ls1 += __shfl_xor_sync(0xffffffffu, ls1, 1);
    ls1 += __shfl_xor_sync(0xffffffffu, ls1, 2);
    const float inv0 = 1.0f / ls0;
    const float inv1 = 1.0f / ls1;

    const int r0 = q0 + wr + g;
#pragma unroll
    for (int nt = 0; nt < 8; nt++) {
        int col = nt * 8 + q4 * 2;
        float2 o0 = make_float2(tf32r(o[nt][0] * inv0), tf32r(o[nt][1] * inv0));
        float2 o1 = make_float2(tf32r(o[nt][2] * inv1), tf32r(o[nt][3] * inv1));
        *(float2*)&O[base + r0 * DD + col] = o0;
        *(float2*)&O[base + (r0 + 8) * DD + col] = o1;
    }
}

// ---------------------------------------------------------------------------
extern "C" void kernel_launch(void* const* d_in, const int* in_sizes, int n_in,
                              void* d_out, int out_size)
{
    const float* hs = (const float*)d_in[0];
    const float* Wq = (const float*)d_in[1];
    const float* bq = (const float*)d_in[2];
    const float* Wk = (const float*)d_in[3];
    const float* bk = (const float*)d_in[4];
    const float* Wv = (const float*)d_in[5];
    const float* bv = (const float*)d_in[6];
    const float* Wo = (const float*)d_in[7];
    const float* bo = (const float*)d_in[8];
    const float* rb = (const float*)d_in[9];

    float *pQ, *pK, *pV, *pA, *pX, *pW;
    cudaGetSymbolAddress((void**)&pQ, g_Q);
    cudaGetSymbolAddress((void**)&pK, g_K);
    cudaGetSymbolAddress((void**)&pV, g_V);
    cudaGetSymbolAddress((void**)&pA, g_AO);
    cudaGetSymbolAddress((void**)&pX, g_Xr);
    cudaGetSymbolAddress((void**)&pW, g_Wr);

    const int NHS4 = BB * TT * DD / 4;   // 1048576
    const int NW4 = DD * DD / 4;         // 65536

    round_kernel<<<NHS4 / 256, 256>>>((const float4*)hs, (float4*)pX, NHS4);
    round_kernel<<<NW4 / 256, 256>>>((const float4*)Wq, (float4*)(pW + 0 * DD * DD), NW4);
    round_kernel<<<NW4 / 256, 256>>>((const float4*)Wk, (float4*)(pW + 1 * DD * DD), NW4);
    round_kernel<<<NW4 / 256, 256>>>((const float4*)Wv, (float4*)(pW + 2 * DD * DD), NW4);
    round_kernel<<<NW4 / 256, 256>>>((const float4*)Wo, (float4*)(pW + 3 * DD * DD), NW4);

    dim3 gg(DD / 64, BB * TT / 64);      // (8, 64)

    gemm_tf32_kernel<<<gg, 128>>>(pX, pW + 0 * DD * DD, bq, pQ, 1);
    gemm_tf32_kernel<<<gg, 128>>>(pX, pW + 1 * DD * DD, bk, pK, 1);
    gemm_tf32_kernel<<<gg, 128>>>(pX, pW + 2 * DD * DD, bv, pV, 1);

    attn_mma_kernel<<<dim3(TT / 64, HH, BB), 128>>>(pQ, pK, pV, rb, pA);

    gemm_tf32_kernel<<<gg, 128>>>(pA, pW + 3 * DD * DD, bo, (float*)d_out, 0);
}

// round 9
// speedup vs baseline: 1.7489x; 1.7489x over previous
#include <cuda_runtime.h>
#include <cuda_fp16.h>
#include <stdint.h>
#include <math.h>

#define TT 2048
#define BB 2
#define DD 512
#define HH 8
#define DH 64
#define MAXREL 32
#define SCALE_L2E 0.1803368801111244f   // (DH^-0.5) * log2(e)
#define L2E 1.4426950408889634f
#define KT 64                           // keys per attention tile
#define NKT (TT / KT)                   // 32 tiles

// Scratch (allocation-free rule: __device__ globals)
__device__ __half g_Qh[BB * TT * DD];
__device__ __half g_Kh[BB * TT * DD];
__device__ __half g_Vh[BB * TT * DD];
__device__ __half g_Vth[BB * HH * DH * TT];   // V transposed [b,h,d,t]
__device__ __half g_AOh[BB * TT * DD];
__device__ __half g_Xh[BB * TT * DD];         // hidden states, half
__device__ __half g_Wth[4 * DD * DD];         // W^T half: [n][k] for q,k,v,o

// ---------------------------------------------------------------------------
// helpers
// ---------------------------------------------------------------------------
__device__ __forceinline__ float ex2(float x) {
    float r;
    asm("ex2.approx.ftz.f32 %0, %1;" : "=f"(r) : "f"(x));
    return r;
}
__device__ __forceinline__ void mma16(float* d, const uint32_t* a, uint32_t b0, uint32_t b1) {
    asm volatile(
        "mma.sync.aligned.m16n8k16.row.col.f32.f16.f16.f32 "
        "{%0,%1,%2,%3}, {%4,%5,%6,%7}, {%8,%9}, {%0,%1,%2,%3};"
        : "+f"(d[0]), "+f"(d[1]), "+f"(d[2]), "+f"(d[3])
        : "r"(a[0]), "r"(a[1]), "r"(a[2]), "r"(a[3]), "r"(b0), "r"(b1));
}
__device__ __forceinline__ uint32_t packh2(float lo, float hi) {
    __half2 h = __floats2half2_rn(lo, hi);
    return *(uint32_t*)&h;
}
__device__ __forceinline__ uint32_t smem_u32(const void* p) {
    uint32_t a;
    asm("{ .reg .u64 t; cvta.to.shared.u64 t, %1; cvt.u32.u64 %0, t; }" : "=r"(a) : "l"(p));
    return a;
}
__device__ __forceinline__ void cpasync16(uint32_t dst, const void* src) {
    asm volatile("cp.async.cg.shared.global [%0], [%1], 16;" :: "r"(dst), "l"(src));
}
#define CP_COMMIT() asm volatile("cp.async.commit_group;" ::: "memory")
#define CP_WAIT1()  asm volatile("cp.async.wait_group 1;" ::: "memory")

// ---------------------------------------------------------------------------
// fp32 -> half elementwise (hidden states)
// ---------------------------------------------------------------------------
__global__ void cvt_half_kernel(const float4* __restrict__ src, __half* __restrict__ dst, int n4)
{
    int i = blockIdx.x * blockDim.x + threadIdx.x;
    if (i < n4) {
        float4 v = src[i];
        __half2 lo = __floats2half2_rn(v.x, v.y);
        __half2 hi = __floats2half2_rn(v.z, v.w);
        uint2 o = make_uint2(*(uint32_t*)&lo, *(uint32_t*)&hi);
        *(uint2*)&dst[i * 4] = o;
    }
}

// ---------------------------------------------------------------------------
// W[k][n] fp32 -> Wt[n][k] half (32x32 tiles)
// ---------------------------------------------------------------------------
__global__ void wtrans_kernel(const float* __restrict__ W, __half* __restrict__ Wt)
{
    __shared__ __half t[32][33];
    const int k0 = blockIdx.x * 32, n0 = blockIdx.y * 32;
    const int tx = threadIdx.x, ty = threadIdx.y;
#pragma unroll
    for (int i = 0; i < 4; i++)
        t[ty + i * 8][tx] = __float2half(W[(size_t)(k0 + ty + i * 8) * DD + n0 + tx]);
    __syncthreads();
#pragma unroll
    for (int i = 0; i < 4; i++)
        Wt[(size_t)(n0 + ty + i * 8) * DD + k0 + tx] = t[tx][ty + i * 8];
}

// ---------------------------------------------------------------------------
// V half [b,t,h*64+d] -> Vt half [b,h,d,t]  (32x32 tiles)
// ---------------------------------------------------------------------------
__global__ void vtrans_kernel(const __half* __restrict__ V, __half* __restrict__ Vt)
{
    __shared__ __half t[32][33];
    const int bh = blockIdx.z;
    const int b = bh >> 3, h = bh & 7;
    const int t0 = blockIdx.x * 32, d0 = blockIdx.y * 32;
    const int tx = threadIdx.x, ty = threadIdx.y;
#pragma unroll
    for (int i = 0; i < 4; i++)
        t[ty + i * 8][tx] = V[(size_t)b * TT * DD + (size_t)(t0 + ty + i * 8) * DD + h * DH + d0 + tx];
    __syncthreads();
#pragma unroll
    for (int i = 0; i < 4; i++)
        Vt[(size_t)(bh * DH + d0 + ty + i * 8) * TT + t0 + tx] = t[tx][ty + i * 8];
}

// ---------------------------------------------------------------------------
// GEMM fp16: C[M,N] = X[M,K] @ Wt[N,K]^T + bias[N].
// BM=64, BN=64, BK=32, 128 threads (4 warps, m16n64). 2-stage cp.async.
// out_half: store half (Q/K/V) else fp32 (final output).
// ---------------------------------------------------------------------------
#define XSP 40                      // halves per row (32 + 8 pad)
#define GXS_H (64 * XSP)            // 2560 halves per tile
#define NKCH 16

__global__ void __launch_bounds__(128) gemm_f16_kernel(
    const __half* __restrict__ X, const __half* __restrict__ Wt,
    const float* __restrict__ bias, void* __restrict__ Cout,
    int out_half)
{
    __shared__ __align__(16) __half sx[2][GXS_H];
    __shared__ __align__(16) __half sw[2][GXS_H];
    __shared__ float bs[64];
    const uint32_t sxb = smem_u32(sx);
    const uint32_t swb = smem_u32(sw);

    const int tid = threadIdx.x;
    const int lane = tid & 31;
    const int wid = tid >> 5;
    const int wr = wid * 16;
    const int g = lane >> 2, q4 = lane & 3;
    const int m0 = blockIdx.y * 64;
    const int n0 = blockIdx.x * 64;

    const int lr = tid >> 2;            // 0..31 (row pairs: +32 for second half)
    const int lc = (tid & 3) * 8;       // halves column (16B chunks)

    // prologue: stage 0 (K rows 64: r and r+32)
#pragma unroll
    for (int half = 0; half < 2; half++) {
        int r = lr + half * 32;
        cpasync16(sxb + (r * XSP + lc) * 2, &X[(size_t)(m0 + r) * DD + lc]);
        cpasync16(swb + (r * XSP + lc) * 2, &Wt[(size_t)(n0 + r) * DD + lc]);
    }
    CP_COMMIT();
    if (tid < 64) bs[tid] = bias[n0 + tid];

    float c[8][4];
#pragma unroll
    for (int nt = 0; nt < 8; nt++)
#pragma unroll
        for (int j = 0; j < 4; j++) c[nt][j] = 0.0f;

    for (int ch = 0; ch < NKCH; ch++) {
        if (ch + 1 < NKCH) {
            const int k0 = (ch + 1) * 32;
            const int st = (ch + 1) & 1;
#pragma unroll
            for (int half = 0; half < 2; half++) {
                int r = lr + half * 32;
                cpasync16(sxb + (st * GXS_H + r * XSP + lc) * 2, &X[(size_t)(m0 + r) * DD + k0 + lc]);
                cpasync16(swb + (st * GXS_H + r * XSP + lc) * 2, &Wt[(size_t)(n0 + r) * DD + k0 + lc]);
            }
        }
        CP_COMMIT();
        CP_WAIT1();
        __syncthreads();

        const __half* Xs = sx[ch & 1];
        const __half* Ws = sw[ch & 1];

#pragma unroll
        for (int ks = 0; ks < 2; ks++) {
            uint32_t a[4];
            const int ac = q4 * 2 + ks * 16;
            a[0] = *(const uint32_t*)&Xs[(wr + g) * XSP + ac];
            a[1] = *(const uint32_t*)&Xs[(wr + g + 8) * XSP + ac];
            a[2] = *(const uint32_t*)&Xs[(wr + g) * XSP + ac + 8];
            a[3] = *(const uint32_t*)&Xs[(wr + g + 8) * XSP + ac + 8];
#pragma unroll
            for (int nt = 0; nt < 8; nt++) {
                uint32_t b0 = *(const uint32_t*)&Ws[(nt * 8 + g) * XSP + ac];
                uint32_t b1 = *(const uint32_t*)&Ws[(nt * 8 + g) * XSP + ac + 8];
                mma16(c[nt], a, b0, b1);
            }
        }
        __syncthreads();
    }

    const int r0 = m0 + wr + g;
    if (out_half) {
        __half* C = (__half*)Cout;
#pragma unroll
        for (int nt = 0; nt < 8; nt++) {
            int col = nt * 8 + q4 * 2;
            uint32_t p0 = packh2(c[nt][0] + bs[col], c[nt][1] + bs[col + 1]);
            uint32_t p1 = packh2(c[nt][2] + bs[col], c[nt][3] + bs[col + 1]);
            *(uint32_t*)&C[(size_t)r0 * DD + n0 + col] = p0;
            *(uint32_t*)&C[(size_t)(r0 + 8) * DD + n0 + col] = p1;
        }
    } else {
        float* C = (float*)Cout;
#pragma unroll
        for (int nt = 0; nt < 8; nt++) {
            int col = nt * 8 + q4 * 2;
            *(float2*)&C[(size_t)r0 * DD + n0 + col] =
                make_float2(c[nt][0] + bs[col], c[nt][1] + bs[col + 1]);
            *(float2*)&C[(size_t)(r0 + 8) * DD + n0 + col] =
                make_float2(c[nt][2] + bs[col], c[nt][3] + bs[col + 1]);
        }
    }
}

// ---------------------------------------------------------------------------
// Attention fp16. Grid (T/128, H, B), 256 threads (8 warps, m16 each).
// Q fragments in registers; K [t][dh] + Vt [dh][t] tiles, 2-stage cp.async.
// S C-fragment == PV A-fragment (fp16 k16) -> no shuffles, no smem P.
// ---------------------------------------------------------------------------
#define KSP 72                      // halves per row (64 + 8 pad)
#define AKT_H (KT * KSP)            // 4608 halves per K or V tile

__global__ void __launch_bounds__(256) attn_f16_kernel(
    const __half* __restrict__ Q, const __half* __restrict__ K,
    const __half* __restrict__ Vt, const float* __restrict__ rb,
    __half* __restrict__ O)
{
    __shared__ __align__(16) __half ks_[2][AKT_H];
    __shared__ __align__(16) __half vs_[2][AKT_H];
    __shared__ float bias_s[72];
    const uint32_t kb = smem_u32(ks_);
    const uint32_t vb = smem_u32(vs_);

    const int tid = threadIdx.x;
    const int lane = tid & 31;
    const int wid = tid >> 5;
    const int wr = wid * 16;
    const int g = lane >> 2, q4 = lane & 3;
    const int q0 = blockIdx.x * 128;
    const int h = blockIdx.y, b = blockIdx.z;
    const int base = b * TT * DD + h * DH;
    const int vtbase = (b * HH + h) * DH * TT;

    const int lr = tid >> 3;            // 0..31 (rows; +32 for second half)
    const int lc = (tid & 7) * 8;       // halves column (16B chunks)

    // prologue: stage 0
#pragma unroll
    for (int half = 0; half < 2; half++) {
        int r = lr + half * 32;
        cpasync16(kb + (r * KSP + lc) * 2, &K[base + r * DD + lc]);
        cpasync16(vb + (r * KSP + lc) * 2, &Vt[vtbase + r * TT + lc]);
    }
    CP_COMMIT();

    if (tid < 2 * MAXREL + 1) bias_s[tid] = rb[h * (2 * MAXREL + 1) + tid] * L2E;
    const float blo = rb[h * (2 * MAXREL + 1)] * L2E;
    const float bhi = rb[h * (2 * MAXREL + 1) + 2 * MAXREL] * L2E;

    // Q fragments in registers (k = 64 dh -> 4 k-steps of 16)
    uint32_t qf[4][4];
#pragma unroll
    for (int ksi = 0; ksi < 4; ksi++) {
        const int ac = q4 * 2 + ksi * 16;
        qf[ksi][0] = *(const uint32_t*)&Q[base + (q0 + wr + g) * DD + ac];
        qf[ksi][1] = *(const uint32_t*)&Q[base + (q0 + wr + g + 8) * DD + ac];
        qf[ksi][2] = *(const uint32_t*)&Q[base + (q0 + wr + g) * DD + ac + 8];
        qf[ksi][3] = *(const uint32_t*)&Q[base + (q0 + wr + g + 8) * DD + ac + 8];
    }

    float o[8][4];
#pragma unroll
    for (int nt = 0; nt < 8; nt++)
#pragma unroll
        for (int j = 0; j < 4; j++) o[nt][j] = 0.0f;
    float ls0 = 0.0f, ls1 = 0.0f;

    const int dr0 = q0 + wr + g;

    for (int kt = 0; kt < NKT; kt++) {
        const int k0 = kt * KT;
        // issue next tile into other buffer
        if (kt + 1 < NKT) {
            const int kn = (kt + 1) * KT;
            const int st = (kt + 1) & 1;
#pragma unroll
            for (int half = 0; half < 2; half++) {
                int r = lr + half * 32;
                cpasync16(kb + (st * AKT_H + r * KSP + lc) * 2, &K[base + (kn + r) * DD + lc]);
                cpasync16(vb + (st * AKT_H + r * KSP + lc) * 2, &Vt[vtbase + r * TT + kn + lc]);
            }
        }
        CP_COMMIT();
        CP_WAIT1();
        __syncthreads();

        const __half* Ks = ks_[kt & 1];
        const __half* Vs = vs_[kt & 1];

        // S = Q K^T  (m=16/warp, n=64 keys, k=64 dh)
        float s[8][4];
#pragma unroll
        for (int nt = 0; nt < 8; nt++)
#pragma unroll
            for (int j = 0; j < 4; j++) s[nt][j] = 0.0f;

#pragma unroll
        for (int ksi = 0; ksi < 4; ksi++) {
            const int ac = q4 * 2 + ksi * 16;
#pragma unroll
            for (int nt = 0; nt < 8; nt++) {
                uint32_t b0 = *(const uint32_t*)&Ks[(nt * 8 + g) * KSP + ac];
                uint32_t b1 = *(const uint32_t*)&Ks[(nt * 8 + g) * KSP + ac + 8];
                mma16(s[nt], qf[ksi], b0, b1);
            }
        }

        // softmax weights: p = exp2(s*scale*l2e + bias*l2e)
        const int dmin = q0 - (k0 + KT - 1);
        const int dmax = q0 + 127 - k0;
        if (dmin >= MAXREL) {
#pragma unroll
            for (int nt = 0; nt < 8; nt++)
#pragma unroll
                for (int j = 0; j < 4; j++) s[nt][j] = ex2(fmaf(s[nt][j], SCALE_L2E, bhi));
        } else if (dmax <= -MAXREL) {
#pragma unroll
            for (int nt = 0; nt < 8; nt++)
#pragma unroll
                for (int j = 0; j < 4; j++) s[nt][j] = ex2(fmaf(s[nt][j], SCALE_L2E, blo));
        } else {
#pragma unroll
            for (int nt = 0; nt < 8; nt++) {
                const int c0 = k0 + nt * 8 + q4 * 2;
#pragma unroll
                for (int j = 0; j < 4; j++) {
                    int rel = (dr0 + ((j >> 1) << 3)) - (c0 + (j & 1));
                    rel = min(max(rel, -MAXREL), MAXREL) + MAXREL;
                    s[nt][j] = ex2(fmaf(s[nt][j], SCALE_L2E, bias_s[rel]));
                }
            }
        }
#pragma unroll
        for (int nt = 0; nt < 8; nt++) {
            ls0 += s[nt][0] + s[nt][1];
            ls1 += s[nt][2] + s[nt][3];
        }

        // O += P V: pack S C-fragments directly into PV A-fragments
#pragma unroll
        for (int ksi = 0; ksi < 4; ksi++) {
            uint32_t a[4];
            a[0] = packh2(s[2 * ksi][0], s[2 * ksi][1]);
            a[1] = packh2(s[2 * ksi][2], s[2 * ksi][3]);
            a[2] = packh2(s[2 * ksi + 1][0], s[2 * ksi + 1][1]);
            a[3] = packh2(s[2 * ksi + 1][2], s[2 * ksi + 1][3]);
            const int ac = q4 * 2 + ksi * 16;
#pragma unroll
            for (int nt = 0; nt < 8; nt++) {
                uint32_t b0 = *(const uint32_t*)&Vs[(nt * 8 + g) * KSP + ac];
                uint32_t b1 = *(const uint32_t*)&Vs[(nt * 8 + g) * KSP + ac + 8];
                mma16(o[nt], a, b0, b1);
            }
        }
        __syncthreads();
    }

    // reduce row sums across the 4 lanes of each quad
    ls0 += __shfl_xor_sync(0xffffffffu, ls0, 1);
    ls0 += __shfl_xor_sync(0xffffffffu, ls0, 2);
    ls1 += __shfl_xor_sync(0xffffffffu, ls1, 1);
    ls1 += __shfl_xor_sync(0xffffffffu, ls1, 2);
    const float inv0 = 1.0f / ls0;
    const float inv1 = 1.0f / ls1;

    const int r0 = q0 + wr + g;
#pragma unroll
    for (int nt = 0; nt < 8; nt++) {
        int col = nt * 8 + q4 * 2;
        uint32_t p0 = packh2(o[nt][0] * inv0, o[nt][1] * inv0);
        uint32_t p1 = packh2(o[nt][2] * inv1, o[nt][3] * inv1);
        *(uint32_t*)&O[base + r0 * DD + col] = p0;
        *(uint32_t*)&O[base + (r0 + 8) * DD + col] = p1;
    }
}

// ---------------------------------------------------------------------------
extern "C" void kernel_launch(void* const* d_in, const int* in_sizes, int n_in,
                              void* d_out, int out_size)
{
    const float* hs = (const float*)d_in[0];
    const float* Wq = (const float*)d_in[1];
    const float* bq = (const float*)d_in[2];
    const float* Wk = (const float*)d_in[3];
    const float* bk = (const float*)d_in[4];
    const float* Wv = (const float*)d_in[5];
    const float* bv = (const float*)d_in[6];
    const float* Wo = (const float*)d_in[7];
    const float* bo = (const float*)d_in[8];
    const float* rb = (const float*)d_in[9];

    __half *pQ, *pK, *pV, *pVt, *pAO, *pX, *pW;
    cudaGetSymbolAddress((void**)&pQ, g_Qh);
    cudaGetSymbolAddress((void**)&pK, g_Kh);
    cudaGetSymbolAddress((void**)&pV, g_Vh);
    cudaGetSymbolAddress((void**)&pVt, g_Vth);
    cudaGetSymbolAddress((void**)&pAO, g_AOh);
    cudaGetSymbolAddress((void**)&pX, g_Xh);
    cudaGetSymbolAddress((void**)&pW, g_Wth);

    const int NHS4 = BB * TT * DD / 4;   // 524288

    cvt_half_kernel<<<NHS4 / 256, 256>>>((const float4*)hs, pX, NHS4);

    dim3 wt(DD / 32, DD / 32);
    wtrans_kernel<<<wt, dim3(32, 8)>>>(Wq, pW + 0 * DD * DD);
    wtrans_kernel<<<wt, dim3(32, 8)>>>(Wk, pW + 1 * DD * DD);
    wtrans_kernel<<<wt, dim3(32, 8)>>>(Wv, pW + 2 * DD * DD);
    wtrans_kernel<<<wt, dim3(32, 8)>>>(Wo, pW + 3 * DD * DD);

    dim3 gg(DD / 64, BB * TT / 64);      // (8, 64)

    gemm_f16_kernel<<<gg, 128>>>(pX, pW + 0 * DD * DD, bq, pQ, 1);
    gemm_f16_kernel<<<gg, 128>>>(pX, pW + 1 * DD * DD, bk, pK, 1);
    gemm_f16_kernel<<<gg, 128>>>(pX, pW + 2 * DD * DD, bv, pV, 1);

    vtrans_kernel<<<dim3(TT / 32, DH / 32, BB * HH), dim3(32, 8)>>>(pV, pVt);

    attn_f16_kernel<<<dim3(TT / 128, HH, BB), 256>>>(pQ, pK, pVt, rb, pAO);

    gemm_f16_kernel<<<gg, 128>>>(pAO, pW + 3 * DD * DD, bo, d_out, 0);
}

// round 10
// speedup vs baseline: 2.0496x; 1.1720x over previous
#include <cuda_runtime.h>
#include <cuda_fp16.h>
#include <stdint.h>
#include <math.h>

#define TT 2048
#define BB 2
#define DD 512
#define HH 8
#define DH 64
#define MAXREL 32
#define SCALE_L2E 0.1803368801111244f   // (DH^-0.5) * log2(e)
#define L2E 1.4426950408889634f
#define KT 64                           // keys per attention tile
#define NKT (TT / KT)                   // 32 tiles

// Scratch (allocation-free rule: __device__ globals)
__device__ __half g_Qh[BB * TT * DD];
__device__ __half g_Kh[BB * TT * DD];
__device__ __half g_Vh[BB * TT * DD];
__device__ __half g_Vth[BB * HH * DH * TT];   // V transposed [b,h,d,t]
__device__ __half g_AOh[BB * TT * DD];
__device__ __half g_Xh[BB * TT * DD];         // hidden states, half
__device__ __half g_Wth[4 * DD * DD];         // W^T half: [n][k] for q,k,v,o

// ---------------------------------------------------------------------------
// helpers
// ---------------------------------------------------------------------------
__device__ __forceinline__ float ex2(float x) {
    float r;
    asm("ex2.approx.ftz.f32 %0, %1;" : "=f"(r) : "f"(x));
    return r;
}
__device__ __forceinline__ void mma16(float* d, const uint32_t* a, uint32_t b0, uint32_t b1) {
    asm volatile(
        "mma.sync.aligned.m16n8k16.row.col.f32.f16.f16.f32 "
        "{%0,%1,%2,%3}, {%4,%5,%6,%7}, {%8,%9}, {%0,%1,%2,%3};"
        : "+f"(d[0]), "+f"(d[1]), "+f"(d[2]), "+f"(d[3])
        : "r"(a[0]), "r"(a[1]), "r"(a[2]), "r"(a[3]), "r"(b0), "r"(b1));
}
__device__ __forceinline__ uint32_t packh2(float lo, float hi) {
    __half2 h = __floats2half2_rn(lo, hi);
    return *(uint32_t*)&h;
}
__device__ __forceinline__ uint32_t smem_u32(const void* p) {
    uint32_t a;
    asm("{ .reg .u64 t; cvta.to.shared.u64 t, %1; cvt.u32.u64 %0, t; }" : "=r"(a) : "l"(p));
    return a;
}
__device__ __forceinline__ void cpasync16(uint32_t dst, const void* src) {
    asm volatile("cp.async.cg.shared.global [%0], [%1], 16;" :: "r"(dst), "l"(src));
}
#define CP_COMMIT() asm volatile("cp.async.commit_group;" ::: "memory")
#define CP_WAIT1()  asm volatile("cp.async.wait_group 1;" ::: "memory")

// ---------------------------------------------------------------------------
// fp32 -> half elementwise (hidden states)
// ---------------------------------------------------------------------------
__global__ void cvt_half_kernel(const float4* __restrict__ src, __half* __restrict__ dst, int n4)
{
    int i = blockIdx.x * blockDim.x + threadIdx.x;
    if (i < n4) {
        float4 v = src[i];
        __half2 lo = __floats2half2_rn(v.x, v.y);
        __half2 hi = __floats2half2_rn(v.z, v.w);
        uint2 o = make_uint2(*(uint32_t*)&lo, *(uint32_t*)&hi);
        *(uint2*)&dst[i * 4] = o;
    }
}

// ---------------------------------------------------------------------------
// Fused: all 4 weight matrices W[k][n] fp32 -> Wt[n][k] half (32x32 tiles)
// ---------------------------------------------------------------------------
__global__ void wtrans4_kernel(const float* __restrict__ W0, const float* __restrict__ W1,
                               const float* __restrict__ W2, const float* __restrict__ W3,
                               __half* __restrict__ Wt)
{
    __shared__ __half t[32][33];
    const int z = blockIdx.z;
    const float* W = (z == 0) ? W0 : (z == 1) ? W1 : (z == 2) ? W2 : W3;
    __half* dst = Wt + (size_t)z * DD * DD;
    const int k0 = blockIdx.x * 32, n0 = blockIdx.y * 32;
    const int tx = threadIdx.x, ty = threadIdx.y;
#pragma unroll
    for (int i = 0; i < 4; i++)
        t[ty + i * 8][tx] = __float2half(W[(size_t)(k0 + ty + i * 8) * DD + n0 + tx]);
    __syncthreads();
#pragma unroll
    for (int i = 0; i < 4; i++)
        dst[(size_t)(n0 + ty + i * 8) * DD + k0 + tx] = t[tx][ty + i * 8];
}

// ---------------------------------------------------------------------------
// V half [b,t,h*64+d] -> Vt half [b,h,d,t]  (32x32 tiles)
// ---------------------------------------------------------------------------
__global__ void vtrans_kernel(const __half* __restrict__ V, __half* __restrict__ Vt)
{
    __shared__ __half t[32][33];
    const int bh = blockIdx.z;
    const int b = bh >> 3, h = bh & 7;
    const int t0 = blockIdx.x * 32, d0 = blockIdx.y * 32;
    const int tx = threadIdx.x, ty = threadIdx.y;
#pragma unroll
    for (int i = 0; i < 4; i++)
        t[ty + i * 8][tx] = V[(size_t)b * TT * DD + (size_t)(t0 + ty + i * 8) * DD + h * DH + d0 + tx];
    __syncthreads();
#pragma unroll
    for (int i = 0; i < 4; i++)
        Vt[(size_t)(bh * DH + d0 + ty + i * 8) * TT + t0 + tx] = t[tx][ty + i * 8];
}

// ---------------------------------------------------------------------------
// GEMM fp16: C[M,N] = X[M,K] @ Wt[N,K]^T + bias[N].
// BM=64, BN=64, BK=64, 128 threads (4 warps, m16n64). 2-stage cp.async.
// ---------------------------------------------------------------------------
#define XSP 72                      // halves per row (64 + 8 pad)
#define GXS_H (64 * XSP)            // 4608 halves per tile
#define NKCH 8

__global__ void __launch_bounds__(128) gemm_f16_kernel(
    const __half* __restrict__ X, const __half* __restrict__ Wt,
    const float* __restrict__ bias, void* __restrict__ Cout,
    int out_half)
{
    __shared__ __align__(16) __half sx[2][GXS_H];
    __shared__ __align__(16) __half sw[2][GXS_H];
    __shared__ float bs[64];
    const uint32_t sxb = smem_u32(sx);
    const uint32_t swb = smem_u32(sw);

    const int tid = threadIdx.x;
    const int lane = tid & 31;
    const int wid = tid >> 5;
    const int wr = wid * 16;
    const int g = lane >> 2, q4 = lane & 3;
    const int m0 = blockIdx.y * 64;
    const int n0 = blockIdx.x * 64;

    const int lr = tid >> 3;            // 0..15
    const int lc = (tid & 7) * 8;       // halves column (16B chunks)

    // prologue: stage 0 (k columns 0..63)
#pragma unroll
    for (int it = 0; it < 4; it++) {
        int r = lr + it * 16;
        cpasync16(sxb + (r * XSP + lc) * 2, &X[(size_t)(m0 + r) * DD + lc]);
        cpasync16(swb + (r * XSP + lc) * 2, &Wt[(size_t)(n0 + r) * DD + lc]);
    }
    CP_COMMIT();
    if (tid < 64) bs[tid] = bias[n0 + tid];

    float c[8][4];
#pragma unroll
    for (int nt = 0; nt < 8; nt++)
#pragma unroll
        for (int j = 0; j < 4; j++) c[nt][j] = 0.0f;

    for (int ch = 0; ch < NKCH; ch++) {
        if (ch + 1 < NKCH) {
            const int k0 = (ch + 1) * 64;
            const int st = (ch + 1) & 1;
#pragma unroll
            for (int it = 0; it < 4; it++) {
                int r = lr + it * 16;
                cpasync16(sxb + (st * GXS_H + r * XSP + lc) * 2, &X[(size_t)(m0 + r) * DD + k0 + lc]);
                cpasync16(swb + (st * GXS_H + r * XSP + lc) * 2, &Wt[(size_t)(n0 + r) * DD + k0 + lc]);
            }
        }
        CP_COMMIT();
        CP_WAIT1();
        __syncthreads();

        const __half* Xs = sx[ch & 1];
        const __half* Ws = sw[ch & 1];

#pragma unroll
        for (int ks = 0; ks < 4; ks++) {
            uint32_t a[4];
            const int ac = q4 * 2 + ks * 16;
            a[0] = *(const uint32_t*)&Xs[(wr + g) * XSP + ac];
            a[1] = *(const uint32_t*)&Xs[(wr + g + 8) * XSP + ac];
            a[2] = *(const uint32_t*)&Xs[(wr + g) * XSP + ac + 8];
            a[3] = *(const uint32_t*)&Xs[(wr + g + 8) * XSP + ac + 8];
#pragma unroll
            for (int nt = 0; nt < 8; nt++) {
                uint32_t b0 = *(const uint32_t*)&Ws[(nt * 8 + g) * XSP + ac];
                uint32_t b1 = *(const uint32_t*)&Ws[(nt * 8 + g) * XSP + ac + 8];
                mma16(c[nt], a, b0, b1);
            }
        }
        __syncthreads();
    }

    const int r0 = m0 + wr + g;
    if (out_half) {
        __half* C = (__half*)Cout;
#pragma unroll
        for (int nt = 0; nt < 8; nt++) {
            int col = nt * 8 + q4 * 2;
            uint32_t p0 = packh2(c[nt][0] + bs[col], c[nt][1] + bs[col + 1]);
            uint32_t p1 = packh2(c[nt][2] + bs[col], c[nt][3] + bs[col + 1]);
            *(uint32_t*)&C[(size_t)r0 * DD + n0 + col] = p0;
            *(uint32_t*)&C[(size_t)(r0 + 8) * DD + n0 + col] = p1;
        }
    } else {
        float* C = (float*)Cout;
#pragma unroll
        for (int nt = 0; nt < 8; nt++) {
            int col = nt * 8 + q4 * 2;
            *(float2*)&C[(size_t)r0 * DD + n0 + col] =
                make_float2(c[nt][0] + bs[col], c[nt][1] + bs[col + 1]);
            *(float2*)&C[(size_t)(r0 + 8) * DD + n0 + col] =
                make_float2(c[nt][2] + bs[col], c[nt][3] + bs[col + 1]);
        }
    }
}

// ---------------------------------------------------------------------------
// Attention fp16. Grid (T/128, H, B), 128 threads (4 warps, m32 each).
// Q fragments in registers; B-fragments shared across the 2 m16 slabs.
// S C-fragment == PV A-fragment -> no shuffles, no smem P.
// ---------------------------------------------------------------------------
#define KSP 72                      // halves per row (64 + 8 pad)
#define AKT_H (KT * KSP)            // 4608 halves per K or V tile

__global__ void __launch_bounds__(128) attn_f16_kernel(
    const __half* __restrict__ Q, const __half* __restrict__ K,
    const __half* __restrict__ Vt, const float* __restrict__ rb,
    __half* __restrict__ O)
{
    __shared__ __align__(16) __half ks_[2][AKT_H];
    __shared__ __align__(16) __half vs_[2][AKT_H];
    __shared__ float bias_s[72];
    const uint32_t kb = smem_u32(ks_);
    const uint32_t vb = smem_u32(vs_);

    const int tid = threadIdx.x;
    const int lane = tid & 31;
    const int wid = tid >> 5;        // 0..3
    const int wr = wid * 32;
    const int g = lane >> 2, q4 = lane & 3;
    const int q0 = blockIdx.x * 128;
    const int h = blockIdx.y, b = blockIdx.z;
    const int base = b * TT * DD + h * DH;
    const int vtbase = (b * HH + h) * DH * TT;

    const int lr = tid >> 3;            // 0..15
    const int lc = (tid & 7) * 8;       // halves column (16B chunks)

    // prologue: stage 0
#pragma unroll
    for (int it = 0; it < 4; it++) {
        int r = lr + it * 16;
        cpasync16(kb + (r * KSP + lc) * 2, &K[base + r * DD + lc]);
        cpasync16(vb + (r * KSP + lc) * 2, &Vt[vtbase + r * TT + lc]);
    }
    CP_COMMIT();

    if (tid < 2 * MAXREL + 1) bias_s[tid] = rb[h * (2 * MAXREL + 1) + tid] * L2E;
    const float blo = rb[h * (2 * MAXREL + 1)] * L2E;
    const float bhi = rb[h * (2 * MAXREL + 1) + 2 * MAXREL] * L2E;

    // Q fragments in registers: 2 slabs x 4 k-steps
    uint32_t qf[2][4][4];
#pragma unroll
    for (int ss = 0; ss < 2; ss++) {
        const int r = q0 + wr + ss * 16 + g;
#pragma unroll
        for (int ksi = 0; ksi < 4; ksi++) {
            const int ac = q4 * 2 + ksi * 16;
            qf[ss][ksi][0] = *(const uint32_t*)&Q[base + r * DD + ac];
            qf[ss][ksi][1] = *(const uint32_t*)&Q[base + (r + 8) * DD + ac];
            qf[ss][ksi][2] = *(const uint32_t*)&Q[base + r * DD + ac + 8];
            qf[ss][ksi][3] = *(const uint32_t*)&Q[base + (r + 8) * DD + ac + 8];
        }
    }

    float o[2][8][4];
#pragma unroll
    for (int ss = 0; ss < 2; ss++)
#pragma unroll
        for (int nt = 0; nt < 8; nt++)
#pragma unroll
            for (int j = 0; j < 4; j++) o[ss][nt][j] = 0.0f;
    float ls[2][2] = {{0.f, 0.f}, {0.f, 0.f}};

    for (int kt = 0; kt < NKT; kt++) {
        const int k0 = kt * KT;
        if (kt + 1 < NKT) {
            const int kn = (kt + 1) * KT;
            const int st = (kt + 1) & 1;
#pragma unroll
            for (int it = 0; it < 4; it++) {
                int r = lr + it * 16;
                cpasync16(kb + (st * AKT_H + r * KSP + lc) * 2, &K[base + (kn + r) * DD + lc]);
                cpasync16(vb + (st * AKT_H + r * KSP + lc) * 2, &Vt[vtbase + r * TT + kn + lc]);
            }
        }
        CP_COMMIT();
        CP_WAIT1();
        __syncthreads();

        const __half* Ks = ks_[kt & 1];
        const __half* Vs = vs_[kt & 1];

        // S = Q K^T  (m=32/warp, n=64 keys, k=64 dh); B-frags shared across slabs
        float s[2][8][4];
#pragma unroll
        for (int ss = 0; ss < 2; ss++)
#pragma unroll
            for (int nt = 0; nt < 8; nt++)
#pragma unroll
                for (int j = 0; j < 4; j++) s[ss][nt][j] = 0.0f;

#pragma unroll
        for (int ksi = 0; ksi < 4; ksi++) {
            const int ac = q4 * 2 + ksi * 16;
#pragma unroll
            for (int nt = 0; nt < 8; nt++) {
                uint32_t b0 = *(const uint32_t*)&Ks[(nt * 8 + g) * KSP + ac];
                uint32_t b1 = *(const uint32_t*)&Ks[(nt * 8 + g) * KSP + ac + 8];
                mma16(s[0][nt], qf[0][ksi], b0, b1);
                mma16(s[1][nt], qf[1][ksi], b0, b1);
            }
        }

        // softmax weights: p = exp2(s*scale*l2e + bias*l2e)
        const int dmin = q0 - (k0 + KT - 1);
        const int dmax = q0 + 127 - k0;
        if (dmin >= MAXREL) {
#pragma unroll
            for (int ss = 0; ss < 2; ss++)
#pragma unroll
                for (int nt = 0; nt < 8; nt++)
#pragma unroll
                    for (int j = 0; j < 4; j++)
                        s[ss][nt][j] = ex2(fmaf(s[ss][nt][j], SCALE_L2E, bhi));
        } else if (dmax <= -MAXREL) {
#pragma unroll
            for (int ss = 0; ss < 2; ss++)
#pragma unroll
                for (int nt = 0; nt < 8; nt++)
#pragma unroll
                    for (int j = 0; j < 4; j++)
                        s[ss][nt][j] = ex2(fmaf(s[ss][nt][j], SCALE_L2E, blo));
        } else {
#pragma unroll
            for (int ss = 0; ss < 2; ss++) {
                const int dr0 = q0 + wr + ss * 16 + g;
#pragma unroll
                for (int nt = 0; nt < 8; nt++) {
                    const int c0 = k0 + nt * 8 + q4 * 2;
#pragma unroll
                    for (int j = 0; j < 4; j++) {
                        int rel = (dr0 + ((j >> 1) << 3)) - (c0 + (j & 1));
                        rel = min(max(rel, -MAXREL), MAXREL) + MAXREL;
                        s[ss][nt][j] = ex2(fmaf(s[ss][nt][j], SCALE_L2E, bias_s[rel]));
                    }
                }
            }
        }
#pragma unroll
        for (int ss = 0; ss < 2; ss++)
#pragma unroll
            for (int nt = 0; nt < 8; nt++) {
                ls[ss][0] += s[ss][nt][0] + s[ss][nt][1];
                ls[ss][1] += s[ss][nt][2] + s[ss][nt][3];
            }

        // O += P V: pack S C-fragments into PV A-fragments; share V B-frags
#pragma unroll
        for (int ksi = 0; ksi < 4; ksi++) {
            uint32_t a0[4], a1[4];
            a0[0] = packh2(s[0][2 * ksi][0], s[0][2 * ksi][1]);
            a0[1] = packh2(s[0][2 * ksi][2], s[0][2 * ksi][3]);
            a0[2] = packh2(s[0][2 * ksi + 1][0], s[0][2 * ksi + 1][1]);
            a0[3] = packh2(s[0][2 * ksi + 1][2], s[0][2 * ksi + 1][3]);
            a1[0] = packh2(s[1][2 * ksi][0], s[1][2 * ksi][1]);
            a1[1] = packh2(s[1][2 * ksi][2], s[1][2 * ksi][3]);
            a1[2] = packh2(s[1][2 * ksi + 1][0], s[1][2 * ksi + 1][1]);
            a1[3] = packh2(s[1][2 * ksi + 1][2], s[1][2 * ksi + 1][3]);
            const int ac = q4 * 2 + ksi * 16;
#pragma unroll
            for (int nt = 0; nt < 8; nt++) {
                uint32_t b0 = *(const uint32_t*)&Vs[(nt * 8 + g) * KSP + ac];
                uint32_t b1 = *(const uint32_t*)&Vs[(nt * 8 + g) * KSP + ac + 8];
                mma16(o[0][nt], a0, b0, b1);
                mma16(o[1][nt], a1, b0, b1);
            }
        }
        __syncthreads();
    }

    // reduce row sums across the 4 lanes of each quad; write O
#pragma unroll
    for (int ss = 0; ss < 2; ss++) {
#pragma unroll
        for (int j = 0; j < 2; j++) {
            ls[ss][j] += __shfl_xor_sync(0xffffffffu, ls[ss][j], 1);
            ls[ss][j] += __shfl_xor_sync(0xffffffffu, ls[ss][j], 2);
        }
        const float inv0 = 1.0f / ls[ss][0];
        const float inv1 = 1.0f / ls[ss][1];
        const int r0 = q0 + wr + ss * 16 + g;
#pragma unroll
        for (int nt = 0; nt < 8; nt++) {
            int col = nt * 8 + q4 * 2;
            uint32_t p0 = packh2(o[ss][nt][0] * inv0, o[ss][nt][1] * inv0);
            uint32_t p1 = packh2(o[ss][nt][2] * inv1, o[ss][nt][3] * inv1);
            *(uint32_t*)&O[base + r0 * DD + col] = p0;
            *(uint32_t*)&O[base + (r0 + 8) * DD + col] = p1;
        }
    }
}

// ---------------------------------------------------------------------------
extern "C" void kernel_launch(void* const* d_in, const int* in_sizes, int n_in,
                              void* d_out, int out_size)
{
    const float* hs = (const float*)d_in[0];
    const float* Wq = (const float*)d_in[1];
    const float* bq = (const float*)d_in[2];
    const float* Wk = (const float*)d_in[3];
    const float* bk = (const float*)d_in[4];
    const float* Wv = (const float*)d_in[5];
    const float* bv = (const float*)d_in[6];
    const float* Wo = (const float*)d_in[7];
    const float* bo = (const float*)d_in[8];
    const float* rb = (const float*)d_in[9];

    __half *pQ, *pK, *pV, *pVt, *pAO, *pX, *pW;
    cudaGetSymbolAddress((void**)&pQ, g_Qh);
    cudaGetSymbolAddress((void**)&pK, g_Kh);
    cudaGetSymbolAddress((void**)&pV, g_Vh);
    cudaGetSymbolAddress((void**)&pVt, g_Vth);
    cudaGetSymbolAddress((void**)&pAO, g_AOh);
    cudaGetSymbolAddress((void**)&pX, g_Xh);
    cudaGetSymbolAddress((void**)&pW, g_Wth);

    const int NHS4 = BB * TT * DD / 4;   // 524288

    cvt_half_kernel<<<NHS4 / 256, 256>>>((const float4*)hs, pX, NHS4);
    wtrans4_kernel<<<dim3(DD / 32, DD / 32, 4), dim3(32, 8)>>>(Wq, Wk, Wv, Wo, pW);

    dim3 gg(DD / 64, BB * TT / 64);      // (8, 64)

    gemm_f16_kernel<<<gg, 128>>>(pX, pW + 0 * DD * DD, bq, pQ, 1);
    gemm_f16_kernel<<<gg, 128>>>(pX, pW + 1 * DD * DD, bk, pK, 1);
    gemm_f16_kernel<<<gg, 128>>>(pX, pW + 2 * DD * DD, bv, pV, 1);

    vtrans_kernel<<<dim3(TT / 32, DH / 32, BB * HH), dim3(32, 8)>>>(pV, pVt);

    attn_f16_kernel<<<dim3(TT / 128, HH, BB), 128>>>(pQ, pK, pVt, rb, pAO);

    gemm_f16_kernel<<<gg, 128>>>(pAO, pW + 3 * DD * DD, bo, d_out, 0);
}

// round 11
// speedup vs baseline: 2.1951x; 1.0710x over previous
#include <cuda_runtime.h>
#include <cuda_fp16.h>
#include <stdint.h>
#include <math.h>

#define TT 2048
#define BB 2
#define DD 512
#define HH 8
#define DH 64
#define MAXREL 32
#define SCALE_L2E 0.1803368801111244f   // (DH^-0.5) * log2(e)
#define L2E 1.4426950408889634f
#define KT 64                           // keys per attention tile
#define NKT (TT / KT)                   // 32 tiles

// Scratch (allocation-free rule: __device__ globals)
__device__ __half g_Qh[BB * TT * DD];
__device__ __half g_Kh[BB * TT * DD];
__device__ __half g_Vh[BB * TT * DD];
__device__ __half g_Vth[BB * HH * DH * TT];   // V transposed [b,h,d,t]
__device__ __half g_AOh[BB * TT * DD];
__device__ __half g_Xh[BB * TT * DD];         // hidden states, half
__device__ __half g_Wth[4 * DD * DD];         // W^T half: [n][k] for q,k,v,o

// ---------------------------------------------------------------------------
// helpers
// ---------------------------------------------------------------------------
__device__ __forceinline__ float ex2(float x) {
    float r;
    asm("ex2.approx.ftz.f32 %0, %1;" : "=f"(r) : "f"(x));
    return r;
}
__device__ __forceinline__ void mma16(float* d, const uint32_t* a, uint32_t b0, uint32_t b1) {
    asm volatile(
        "mma.sync.aligned.m16n8k16.row.col.f32.f16.f16.f32 "
        "{%0,%1,%2,%3}, {%4,%5,%6,%7}, {%8,%9}, {%0,%1,%2,%3};"
        : "+f"(d[0]), "+f"(d[1]), "+f"(d[2]), "+f"(d[3])
        : "r"(a[0]), "r"(a[1]), "r"(a[2]), "r"(a[3]), "r"(b0), "r"(b1));
}
__device__ __forceinline__ uint32_t packh2(float lo, float hi) {
    __half2 h = __floats2half2_rn(lo, hi);
    return *(uint32_t*)&h;
}
__device__ __forceinline__ uint32_t smem_u32(const void* p) {
    uint32_t a;
    asm("{ .reg .u64 t; cvta.to.shared.u64 t, %1; cvt.u32.u64 %0, t; }" : "=r"(a) : "l"(p));
    return a;
}
__device__ __forceinline__ void cpasync16(uint32_t dst, const void* src) {
    asm volatile("cp.async.cg.shared.global [%0], [%1], 16;" :: "r"(dst), "l"(src));
}
#define CP_COMMIT() asm volatile("cp.async.commit_group;" ::: "memory")
#define CP_WAIT1()  asm volatile("cp.async.wait_group 1;" ::: "memory")

// ---------------------------------------------------------------------------
// fp32 -> half elementwise (hidden states)
// ---------------------------------------------------------------------------
__global__ void cvt_half_kernel(const float4* __restrict__ src, __half* __restrict__ dst, int n4)
{
    int i = blockIdx.x * blockDim.x + threadIdx.x;
    if (i < n4) {
        float4 v = src[i];
        __half2 lo = __floats2half2_rn(v.x, v.y);
        __half2 hi = __floats2half2_rn(v.z, v.w);
        uint2 o = make_uint2(*(uint32_t*)&lo, *(uint32_t*)&hi);
        *(uint2*)&dst[i * 4] = o;
    }
}

// ---------------------------------------------------------------------------
// Fused: all 4 weight matrices W[k][n] fp32 -> Wt[n][k] half (32x32 tiles)
// ---------------------------------------------------------------------------
__global__ void wtrans4_kernel(const float* __restrict__ W0, const float* __restrict__ W1,
                               const float* __restrict__ W2, const float* __restrict__ W3,
                               __half* __restrict__ Wt)
{
    __shared__ __half t[32][33];
    const int z = blockIdx.z;
    const float* W = (z == 0) ? W0 : (z == 1) ? W1 : (z == 2) ? W2 : W3;
    __half* dst = Wt + (size_t)z * DD * DD;
    const int k0 = blockIdx.x * 32, n0 = blockIdx.y * 32;
    const int tx = threadIdx.x, ty = threadIdx.y;
#pragma unroll
    for (int i = 0; i < 4; i++)
        t[ty + i * 8][tx] = __float2half(W[(size_t)(k0 + ty + i * 8) * DD + n0 + tx]);
    __syncthreads();
#pragma unroll
    for (int i = 0; i < 4; i++)
        dst[(size_t)(n0 + ty + i * 8) * DD + k0 + tx] = t[tx][ty + i * 8];
}

// ---------------------------------------------------------------------------
// V half [b,t,h*64+d] -> Vt half [b,h,d,t]  (32x32 tiles)
// ---------------------------------------------------------------------------
__global__ void vtrans_kernel(const __half* __restrict__ V, __half* __restrict__ Vt)
{
    __shared__ __half t[32][33];
    const int bh = blockIdx.z;
    const int b = bh >> 3, h = bh & 7;
    const int t0 = blockIdx.x * 32, d0 = blockIdx.y * 32;
    const int tx = threadIdx.x, ty = threadIdx.y;
#pragma unroll
    for (int i = 0; i < 4; i++)
        t[ty + i * 8][tx] = V[(size_t)b * TT * DD + (size_t)(t0 + ty + i * 8) * DD + h * DH + d0 + tx];
    __syncthreads();
#pragma unroll
    for (int i = 0; i < 4; i++)
        Vt[(size_t)(bh * DH + d0 + ty + i * 8) * TT + t0 + tx] = t[tx][ty + i * 8];
}

// ---------------------------------------------------------------------------
// GEMM fp16: C[M,N] = X[M,K] @ Wt[N,K]^T + bias[N].
// BM=64, BN=128, BK=64, 128 threads (4 warps, m16n128). 2-stage cp.async.
// grid.z selects weight slab (wbase+z), bias, and output.
// ---------------------------------------------------------------------------
#define XSP 72                       // halves per row (64 + 8 pad)
#define XT_H (64 * XSP)              // 4608
#define WT_H (128 * XSP)             // 9216
#define GEMM_SMEM_B ((2 * XT_H + 2 * WT_H) * 2 + 512 + 16)
#define NKCH 8

__global__ void __launch_bounds__(128) gemm_f16_kernel(
    const __half* __restrict__ X, const __half* __restrict__ WtBase, int wbase,
    const float* __restrict__ b0p, const float* __restrict__ b1p, const float* __restrict__ b2p,
    void* __restrict__ o0p, void* __restrict__ o1p, void* __restrict__ o2p,
    int out_half)
{
    extern __shared__ __align__(16) __half smh[];
    __half* sx = smh;                      // [2][XT_H]
    __half* sw = smh + 2 * XT_H;           // [2][WT_H]
    float* bs = (float*)(smh + 2 * XT_H + 2 * WT_H);
    const uint32_t sxb = smem_u32(sx);
    const uint32_t swb = smem_u32(sw);

    const int z = blockIdx.z;
    const __half* Wt = WtBase + (size_t)(wbase + z) * DD * DD;
    const float* bias = (z == 0) ? b0p : (z == 1) ? b1p : b2p;
    void* Cout = (z == 0) ? o0p : (z == 1) ? o1p : o2p;

    const int tid = threadIdx.x;
    const int lane = tid & 31;
    const int wid = tid >> 5;
    const int wr = wid * 16;
    const int g = lane >> 2, q4 = lane & 3;
    const int m0 = blockIdx.y * 64;
    const int n0 = blockIdx.x * 128;

    const int lr = tid >> 3;            // 0..15
    const int lc = (tid & 7) * 8;       // halves column (16B chunks)

    // prologue: stage 0 (k columns 0..63)
#pragma unroll
    for (int it = 0; it < 4; it++) {
        int r = lr + it * 16;
        cpasync16(sxb + (r * XSP + lc) * 2, &X[(size_t)(m0 + r) * DD + lc]);
    }
#pragma unroll
    for (int it = 0; it < 8; it++) {
        int r = lr + it * 16;
        cpasync16(swb + (r * XSP + lc) * 2, &Wt[(size_t)(n0 + r) * DD + lc]);
    }
    CP_COMMIT();
    if (tid < 128) bs[tid] = bias[n0 + tid];

    float c[16][4];
#pragma unroll
    for (int nt = 0; nt < 16; nt++)
#pragma unroll
        for (int j = 0; j < 4; j++) c[nt][j] = 0.0f;

    for (int ch = 0; ch < NKCH; ch++) {
        if (ch + 1 < NKCH) {
            const int k0 = (ch + 1) * 64;
            const int st = (ch + 1) & 1;
#pragma unroll
            for (int it = 0; it < 4; it++) {
                int r = lr + it * 16;
                cpasync16(sxb + (st * XT_H + r * XSP + lc) * 2, &X[(size_t)(m0 + r) * DD + k0 + lc]);
            }
#pragma unroll
            for (int it = 0; it < 8; it++) {
                int r = lr + it * 16;
                cpasync16(swb + (st * WT_H + r * XSP + lc) * 2, &Wt[(size_t)(n0 + r) * DD + k0 + lc]);
            }
        }
        CP_COMMIT();
        CP_WAIT1();
        __syncthreads();

        const __half* Xs = sx + (ch & 1) * XT_H;
        const __half* Ws = sw + (ch & 1) * WT_H;

#pragma unroll
        for (int ks = 0; ks < 4; ks++) {
            uint32_t a[4];
            const int ac = q4 * 2 + ks * 16;
            a[0] = *(const uint32_t*)&Xs[(wr + g) * XSP + ac];
            a[1] = *(const uint32_t*)&Xs[(wr + g + 8) * XSP + ac];
            a[2] = *(const uint32_t*)&Xs[(wr + g) * XSP + ac + 8];
            a[3] = *(const uint32_t*)&Xs[(wr + g + 8) * XSP + ac + 8];
#pragma unroll
            for (int nt = 0; nt < 16; nt++) {
                uint32_t b0 = *(const uint32_t*)&Ws[(nt * 8 + g) * XSP + ac];
                uint32_t b1 = *(const uint32_t*)&Ws[(nt * 8 + g) * XSP + ac + 8];
                mma16(c[nt], a, b0, b1);
            }
        }
        __syncthreads();
    }

    const int r0 = m0 + wr + g;
    if (out_half) {
        __half* C = (__half*)Cout;
#pragma unroll
        for (int nt = 0; nt < 16; nt++) {
            int col = n0 + nt * 8 + q4 * 2;
            int bcol = nt * 8 + q4 * 2;
            uint32_t p0 = packh2(c[nt][0] + bs[bcol], c[nt][1] + bs[bcol + 1]);
            uint32_t p1 = packh2(c[nt][2] + bs[bcol], c[nt][3] + bs[bcol + 1]);
            *(uint32_t*)&C[(size_t)r0 * DD + col] = p0;
            *(uint32_t*)&C[(size_t)(r0 + 8) * DD + col] = p1;
        }
    } else {
        float* C = (float*)Cout;
#pragma unroll
        for (int nt = 0; nt < 16; nt++) {
            int col = n0 + nt * 8 + q4 * 2;
            int bcol = nt * 8 + q4 * 2;
            *(float2*)&C[(size_t)r0 * DD + col] =
                make_float2(c[nt][0] + bs[bcol], c[nt][1] + bs[bcol + 1]);
            *(float2*)&C[(size_t)(r0 + 8) * DD + col] =
                make_float2(c[nt][2] + bs[bcol], c[nt][3] + bs[bcol + 1]);
        }
    }
}

// ---------------------------------------------------------------------------
// Attention fp16. Grid (T/128, H, B), 128 threads (4 warps, m32 each).
// (unchanged from R10)
// ---------------------------------------------------------------------------
#define KSP 72                      // halves per row (64 + 8 pad)
#define AKT_H (KT * KSP)            // 4608 halves per K or V tile

__global__ void __launch_bounds__(128) attn_f16_kernel(
    const __half* __restrict__ Q, const __half* __restrict__ K,
    const __half* __restrict__ Vt, const float* __restrict__ rb,
    __half* __restrict__ O)
{
    __shared__ __align__(16) __half ks_[2][AKT_H];
    __shared__ __align__(16) __half vs_[2][AKT_H];
    __shared__ float bias_s[72];
    const uint32_t kb = smem_u32(ks_);
    const uint32_t vb = smem_u32(vs_);

    const int tid = threadIdx.x;
    const int lane = tid & 31;
    const int wid = tid >> 5;        // 0..3
    const int wr = wid * 32;
    const int g = lane >> 2, q4 = lane & 3;
    const int q0 = blockIdx.x * 128;
    const int h = blockIdx.y, b = blockIdx.z;
    const int base = b * TT * DD + h * DH;
    const int vtbase = (b * HH + h) * DH * TT;

    const int lr = tid >> 3;            // 0..15
    const int lc = (tid & 7) * 8;       // halves column (16B chunks)

    // prologue: stage 0
#pragma unroll
    for (int it = 0; it < 4; it++) {
        int r = lr + it * 16;
        cpasync16(kb + (r * KSP + lc) * 2, &K[base + r * DD + lc]);
        cpasync16(vb + (r * KSP + lc) * 2, &Vt[vtbase + r * TT + lc]);
    }
    CP_COMMIT();

    if (tid < 2 * MAXREL + 1) bias_s[tid] = rb[h * (2 * MAXREL + 1) + tid] * L2E;
    const float blo = rb[h * (2 * MAXREL + 1)] * L2E;
    const float bhi = rb[h * (2 * MAXREL + 1) + 2 * MAXREL] * L2E;

    // Q fragments in registers: 2 slabs x 4 k-steps
    uint32_t qf[2][4][4];
#pragma unroll
    for (int ss = 0; ss < 2; ss++) {
        const int r = q0 + wr + ss * 16 + g;
#pragma unroll
        for (int ksi = 0; ksi < 4; ksi++) {
            const int ac = q4 * 2 + ksi * 16;
            qf[ss][ksi][0] = *(const uint32_t*)&Q[base + r * DD + ac];
            qf[ss][ksi][1] = *(const uint32_t*)&Q[base + (r + 8) * DD + ac];
            qf[ss][ksi][2] = *(const uint32_t*)&Q[base + r * DD + ac + 8];
            qf[ss][ksi][3] = *(const uint32_t*)&Q[base + (r + 8) * DD + ac + 8];
        }
    }

    float o[2][8][4];
#pragma unroll
    for (int ss = 0; ss < 2; ss++)
#pragma unroll
        for (int nt = 0; nt < 8; nt++)
#pragma unroll
            for (int j = 0; j < 4; j++) o[ss][nt][j] = 0.0f;
    float ls[2][2] = {{0.f, 0.f}, {0.f, 0.f}};

    for (int kt = 0; kt < NKT; kt++) {
        const int k0 = kt * KT;
        if (kt + 1 < NKT) {
            const int kn = (kt + 1) * KT;
            const int st = (kt + 1) & 1;
#pragma unroll
            for (int it = 0; it < 4; it++) {
                int r = lr + it * 16;
                cpasync16(kb + (st * AKT_H + r * KSP + lc) * 2, &K[base + (kn + r) * DD + lc]);
                cpasync16(vb + (st * AKT_H + r * KSP + lc) * 2, &Vt[vtbase + r * TT + kn + lc]);
            }
        }
        CP_COMMIT();
        CP_WAIT1();
        __syncthreads();

        const __half* Ks = ks_[kt & 1];
        const __half* Vs = vs_[kt & 1];

        float s[2][8][4];
#pragma unroll
        for (int ss = 0; ss < 2; ss++)
#pragma unroll
            for (int nt = 0; nt < 8; nt++)
#pragma unroll
                for (int j = 0; j < 4; j++) s[ss][nt][j] = 0.0f;

#pragma unroll
        for (int ksi = 0; ksi < 4; ksi++) {
            const int ac = q4 * 2 + ksi * 16;
#pragma unroll
            for (int nt = 0; nt < 8; nt++) {
                uint32_t b0 = *(const uint32_t*)&Ks[(nt * 8 + g) * KSP + ac];
                uint32_t b1 = *(const uint32_t*)&Ks[(nt * 8 + g) * KSP + ac + 8];
                mma16(s[0][nt], qf[0][ksi], b0, b1);
                mma16(s[1][nt], qf[1][ksi], b0, b1);
            }
        }

        const int dmin = q0 - (k0 + KT - 1);
        const int dmax = q0 + 127 - k0;
        if (dmin >= MAXREL) {
#pragma unroll
            for (int ss = 0; ss < 2; ss++)
#pragma unroll
                for (int nt = 0; nt < 8; nt++)
#pragma unroll
                    for (int j = 0; j < 4; j++)
                        s[ss][nt][j] = ex2(fmaf(s[ss][nt][j], SCALE_L2E, bhi));
        } else if (dmax <= -MAXREL) {
#pragma unroll
            for (int ss = 0; ss < 2; ss++)
#pragma unroll
                for (int nt = 0; nt < 8; nt++)
#pragma unroll
                    for (int j = 0; j < 4; j++)
                        s[ss][nt][j] = ex2(fmaf(s[ss][nt][j], SCALE_L2E, blo));
        } else {
#pragma unroll
            for (int ss = 0; ss < 2; ss++) {
                const int dr0 = q0 + wr + ss * 16 + g;
#pragma unroll
                for (int nt = 0; nt < 8; nt++) {
                    const int c0 = k0 + nt * 8 + q4 * 2;
#pragma unroll
                    for (int j = 0; j < 4; j++) {
                        int rel = (dr0 + ((j >> 1) << 3)) - (c0 + (j & 1));
                        rel = min(max(rel, -MAXREL), MAXREL) + MAXREL;
                        s[ss][nt][j] = ex2(fmaf(s[ss][nt][j], SCALE_L2E, bias_s[rel]));
                    }
                }
            }
        }
#pragma unroll
        for (int ss = 0; ss < 2; ss++)
#pragma unroll
            for (int nt = 0; nt < 8; nt++) {
                ls[ss][0] += s[ss][nt][0] + s[ss][nt][1];
                ls[ss][1] += s[ss][nt][2] + s[ss][nt][3];
            }

#pragma unroll
        for (int ksi = 0; ksi < 4; ksi++) {
            uint32_t a0[4], a1[4];
            a0[0] = packh2(s[0][2 * ksi][0], s[0][2 * ksi][1]);
            a0[1] = packh2(s[0][2 * ksi][2], s[0][2 * ksi][3]);
            a0[2] = packh2(s[0][2 * ksi + 1][0], s[0][2 * ksi + 1][1]);
            a0[3] = packh2(s[0][2 * ksi + 1][2], s[0][2 * ksi + 1][3]);
            a1[0] = packh2(s[1][2 * ksi][0], s[1][2 * ksi][1]);
            a1[1] = packh2(s[1][2 * ksi][2], s[1][2 * ksi][3]);
            a1[2] = packh2(s[1][2 * ksi + 1][0], s[1][2 * ksi + 1][1]);
            a1[3] = packh2(s[1][2 * ksi + 1][2], s[1][2 * ksi + 1][3]);
            const int ac = q4 * 2 + ksi * 16;
#pragma unroll
            for (int nt = 0; nt < 8; nt++) {
                uint32_t b0 = *(const uint32_t*)&Vs[(nt * 8 + g) * KSP + ac];
                uint32_t b1 = *(const uint32_t*)&Vs[(nt * 8 + g) * KSP + ac + 8];
                mma16(o[0][nt], a0, b0, b1);
                mma16(o[1][nt], a1, b0, b1);
            }
        }
        __syncthreads();
    }

#pragma unroll
    for (int ss = 0; ss < 2; ss++) {
#pragma unroll
        for (int j = 0; j < 2; j++) {
            ls[ss][j] += __shfl_xor_sync(0xffffffffu, ls[ss][j], 1);
            ls[ss][j] += __shfl_xor_sync(0xffffffffu, ls[ss][j], 2);
        }
        const float inv0 = 1.0f / ls[ss][0];
        const float inv1 = 1.0f / ls[ss][1];
        const int r0 = q0 + wr + ss * 16 + g;
#pragma unroll
        for (int nt = 0; nt < 8; nt++) {
            int col = nt * 8 + q4 * 2;
            uint32_t p0 = packh2(o[ss][nt][0] * inv0, o[ss][nt][1] * inv0);
            uint32_t p1 = packh2(o[ss][nt][2] * inv1, o[ss][nt][3] * inv1);
            *(uint32_t*)&O[base + r0 * DD + col] = p0;
            *(uint32_t*)&O[base + (r0 + 8) * DD + col] = p1;
        }
    }
}

// ---------------------------------------------------------------------------
extern "C" void kernel_launch(void* const* d_in, const int* in_sizes, int n_in,
                              void* d_out, int out_size)
{
    const float* hs = (const float*)d_in[0];
    const float* Wq = (const float*)d_in[1];
    const float* bq = (const float*)d_in[2];
    const float* Wk = (const float*)d_in[3];
    const float* bk = (const float*)d_in[4];
    const float* Wv = (const float*)d_in[5];
    const float* bv = (const float*)d_in[6];
    const float* Wo = (const float*)d_in[7];
    const float* bo = (const float*)d_in[8];
    const float* rb = (const float*)d_in[9];

    __half *pQ, *pK, *pV, *pVt, *pAO, *pX, *pW;
    cudaGetSymbolAddress((void**)&pQ, g_Qh);
    cudaGetSymbolAddress((void**)&pK, g_Kh);
    cudaGetSymbolAddress((void**)&pV, g_Vh);
    cudaGetSymbolAddress((void**)&pVt, g_Vth);
    cudaGetSymbolAddress((void**)&pAO, g_AOh);
    cudaGetSymbolAddress((void**)&pX, g_Xh);
    cudaGetSymbolAddress((void**)&pW, g_Wth);

    cudaFuncSetAttribute(gemm_f16_kernel,
                         cudaFuncAttributeMaxDynamicSharedMemorySize, GEMM_SMEM_B);

    const int NHS4 = BB * TT * DD / 4;   // 524288

    cvt_half_kernel<<<NHS4 / 256, 256>>>((const float4*)hs, pX, NHS4);
    wtrans4_kernel<<<dim3(DD / 32, DD / 32, 4), dim3(32, 8)>>>(Wq, Wk, Wv, Wo, pW);

    // Fused Q/K/V projections: grid.z selects weight/bias/output
    gemm_f16_kernel<<<dim3(DD / 128, BB * TT / 64, 3), 128, GEMM_SMEM_B>>>(
        pX, pW, 0, bq, bk, bv, pQ, pK, pV, 1);

    vtrans_kernel<<<dim3(TT / 32, DH / 32, BB * HH), dim3(32, 8)>>>(pV, pVt);

    attn_f16_kernel<<<dim3(TT / 128, HH, BB), 128>>>(pQ, pK, pVt, rb, pAO);

    // Output projection (z=0 slot carries Wo via wbase=3, fp32 out)
    gemm_f16_kernel<<<dim3(DD / 128, BB * TT / 64, 1), 128, GEMM_SMEM_B>>>(
        pAO, pW, 3, bo, bo, bo, d_out, d_out, d_out, 0);
}

// round 12
// speedup vs baseline: 2.3768x; 1.0828x over previous
#include <cuda_runtime.h>
#include <cuda_fp16.h>
#include <stdint.h>
#include <math.h>

#define TT 2048
#define BB 2
#define DD 512
#define HH 8
#define DH 64
#define MAXREL 32
#define SCALE_L2E 0.1803368801111244f   // (DH^-0.5) * log2(e)
#define L2E 1.4426950408889634f
#define KT 64                           // keys per attention tile
#define NKT (TT / KT)                   // 32 tiles

// Scratch (allocation-free rule: __device__ globals)
__device__ __half g_Qh[BB * TT * DD];
__device__ __half g_Kh[BB * TT * DD];
__device__ __half g_Vth[BB * HH * DH * TT];   // V transposed [b,h,d,t]
__device__ __half g_AOh[BB * TT * DD];
__device__ __half g_Xh[BB * TT * DD];         // hidden states, half
__device__ __half g_Wth[4 * DD * DD];         // W^T half: [n][k] for q,k,v,o

// ---------------------------------------------------------------------------
// helpers
// ---------------------------------------------------------------------------
__device__ __forceinline__ float ex2(float x) {
    float r;
    asm("ex2.approx.ftz.f32 %0, %1;" : "=f"(r) : "f"(x));
    return r;
}
__device__ __forceinline__ void mma16(float* d, const uint32_t* a, uint32_t b0, uint32_t b1) {
    asm volatile(
        "mma.sync.aligned.m16n8k16.row.col.f32.f16.f16.f32 "
        "{%0,%1,%2,%3}, {%4,%5,%6,%7}, {%8,%9}, {%0,%1,%2,%3};"
        : "+f"(d[0]), "+f"(d[1]), "+f"(d[2]), "+f"(d[3])
        : "r"(a[0]), "r"(a[1]), "r"(a[2]), "r"(a[3]), "r"(b0), "r"(b1));
}
__device__ __forceinline__ void ldsm4(uint32_t& r0, uint32_t& r1, uint32_t& r2, uint32_t& r3,
                                      uint32_t addr) {
    asm volatile("ldmatrix.sync.aligned.m8n8.x4.shared.b16 {%0,%1,%2,%3}, [%4];"
                 : "=r"(r0), "=r"(r1), "=r"(r2), "=r"(r3) : "r"(addr));
}
__device__ __forceinline__ uint32_t packh2(float lo, float hi) {
    __half2 h = __floats2half2_rn(lo, hi);
    return *(uint32_t*)&h;
}
__device__ __forceinline__ uint32_t smem_u32(const void* p) {
    uint32_t a;
    asm("{ .reg .u64 t; cvta.to.shared.u64 t, %1; cvt.u32.u64 %0, t; }" : "=r"(a) : "l"(p));
    return a;
}
__device__ __forceinline__ void cpasync16(uint32_t dst, const void* src) {
    asm volatile("cp.async.cg.shared.global [%0], [%1], 16;" :: "r"(dst), "l"(src));
}
#define CP_COMMIT() asm volatile("cp.async.commit_group;" ::: "memory")
#define CP_WAIT1()  asm volatile("cp.async.wait_group 1;" ::: "memory")

// ---------------------------------------------------------------------------
// Fused prep: z=0..3 -> W[k][n] fp32 -> Wt[n][k] half; z=4 -> hs fp32 -> half
// ---------------------------------------------------------------------------
__global__ void prep_kernel(const float* __restrict__ hs,
                            const float* __restrict__ W0, const float* __restrict__ W1,
                            const float* __restrict__ W2, const float* __restrict__ W3,
                            __half* __restrict__ Xh, __half* __restrict__ Wt)
{
    const int z = blockIdx.z;
    const int tx = threadIdx.x, ty = threadIdx.y;
    if (z == 4) {
        // hs convert: 2M floats = 524288 float4; 256 blocks x 256 thr x 8
        const int tidf = ty * 32 + tx;
        const int gb = blockIdx.y * gridDim.x + blockIdx.x;   // 0..255
        const float4* src = (const float4*)hs;
#pragma unroll
        for (int j = 0; j < 8; j++) {
            int i = gb * 2048 + j * 256 + tidf;
            float4 v = src[i];
            __half2 lo = __floats2half2_rn(v.x, v.y);
            __half2 hi = __floats2half2_rn(v.z, v.w);
            uint2 o = make_uint2(*(uint32_t*)&lo, *(uint32_t*)&hi);
            *(uint2*)&Xh[i * 4] = o;
        }
        return;
    }
    __shared__ __half t[32][33];
    const float* W = (z == 0) ? W0 : (z == 1) ? W1 : (z == 2) ? W2 : W3;
    __half* dst = Wt + (size_t)z * DD * DD;
    const int k0 = blockIdx.x * 32, n0 = blockIdx.y * 32;
#pragma unroll
    for (int i = 0; i < 4; i++)
        t[ty + i * 8][tx] = __float2half(W[(size_t)(k0 + ty + i * 8) * DD + n0 + tx]);
    __syncthreads();
#pragma unroll
    for (int i = 0; i < 4; i++)
        dst[(size_t)(n0 + ty + i * 8) * DD + k0 + tx] = t[tx][ty + i * 8];
}

// ---------------------------------------------------------------------------
// GEMM fp16: C[M,N] = X[M,K] @ Wt[N,K]^T + bias[N].
// BM=64, BN=128, BK=64, 128 threads. grid.z selects weight/bias/output.
// z == vtz -> write output TRANSPOSED per head into Vt [b,h,d,t] (fused vtrans).
// ---------------------------------------------------------------------------
#define XSP 72                       // halves per row (64 + 8 pad)
#define XT_H (64 * XSP)              // 4608
#define WT_H (128 * XSP)             // 9216
#define GEMM_SMEM_B ((2 * XT_H + 2 * WT_H) * 2 + 512 + 16)
#define NKCH 8

__global__ void __launch_bounds__(128) gemm_f16_kernel(
    const __half* __restrict__ X, const __half* __restrict__ WtBase, int wbase,
    const float* __restrict__ b0p, const float* __restrict__ b1p, const float* __restrict__ b2p,
    void* __restrict__ o0p, void* __restrict__ o1p, void* __restrict__ o2p,
    int out_half, int vtz)
{
    extern __shared__ __align__(16) __half smh[];
    __half* sx = smh;                      // [2][XT_H]
    __half* sw = smh + 2 * XT_H;           // [2][WT_H]
    float* bs = (float*)(smh + 2 * XT_H + 2 * WT_H);
    const uint32_t sxb = smem_u32(sx);
    const uint32_t swb = smem_u32(sw);

    const int z = blockIdx.z;
    const __half* Wt = WtBase + (size_t)(wbase + z) * DD * DD;
    const float* bias = (z == 0) ? b0p : (z == 1) ? b1p : b2p;
    void* Cout = (z == 0) ? o0p : (z == 1) ? o1p : o2p;

    const int tid = threadIdx.x;
    const int lane = tid & 31;
    const int wid = tid >> 5;
    const int wr = wid * 16;
    const int g = lane >> 2, q4 = lane & 3;
    const int m0 = blockIdx.y * 64;
    const int n0 = blockIdx.x * 128;

    const int lr = tid >> 3;            // 0..15
    const int lc = (tid & 7) * 8;       // halves column (16B chunks)

    // prologue: stage 0 (k columns 0..63)
#pragma unroll
    for (int it = 0; it < 4; it++) {
        int r = lr + it * 16;
        cpasync16(sxb + (r * XSP + lc) * 2, &X[(size_t)(m0 + r) * DD + lc]);
    }
#pragma unroll
    for (int it = 0; it < 8; it++) {
        int r = lr + it * 16;
        cpasync16(swb + (r * XSP + lc) * 2, &Wt[(size_t)(n0 + r) * DD + lc]);
    }
    CP_COMMIT();
    if (tid < 128) bs[tid] = bias[n0 + tid];

    float c[16][4];
#pragma unroll
    for (int nt = 0; nt < 16; nt++)
#pragma unroll
        for (int j = 0; j < 4; j++) c[nt][j] = 0.0f;

    for (int ch = 0; ch < NKCH; ch++) {
        if (ch + 1 < NKCH) {
            const int k0 = (ch + 1) * 64;
            const int st = (ch + 1) & 1;
#pragma unroll
            for (int it = 0; it < 4; it++) {
                int r = lr + it * 16;
                cpasync16(sxb + (st * XT_H + r * XSP + lc) * 2, &X[(size_t)(m0 + r) * DD + k0 + lc]);
            }
#pragma unroll
            for (int it = 0; it < 8; it++) {
                int r = lr + it * 16;
                cpasync16(swb + (st * WT_H + r * XSP + lc) * 2, &Wt[(size_t)(n0 + r) * DD + k0 + lc]);
            }
        }
        CP_COMMIT();
        CP_WAIT1();
        __syncthreads();

        const __half* Xs = sx + (ch & 1) * XT_H;
        const __half* Ws = sw + (ch & 1) * WT_H;

#pragma unroll
        for (int ks = 0; ks < 4; ks++) {
            uint32_t a[4];
            const int ac = q4 * 2 + ks * 16;
            a[0] = *(const uint32_t*)&Xs[(wr + g) * XSP + ac];
            a[1] = *(const uint32_t*)&Xs[(wr + g + 8) * XSP + ac];
            a[2] = *(const uint32_t*)&Xs[(wr + g) * XSP + ac + 8];
            a[3] = *(const uint32_t*)&Xs[(wr + g + 8) * XSP + ac + 8];
#pragma unroll
            for (int nt = 0; nt < 16; nt++) {
                uint32_t b0 = *(const uint32_t*)&Ws[(nt * 8 + g) * XSP + ac];
                uint32_t b1 = *(const uint32_t*)&Ws[(nt * 8 + g) * XSP + ac + 8];
                mma16(c[nt], a, b0, b1);
            }
        }
        __syncthreads();
    }

    const int r0 = m0 + wr + g;
    if (z == vtz) {
        // Fused V transpose: stage [col][t_local] (pitch 72), then write Vt [b,h,d,t]
        __half* stg = smh;   // 128*72 = 9216 halves = 2*XT_H (x buffers, free now)
        const int rl = wr + g;
#pragma unroll
        for (int nt = 0; nt < 16; nt++) {
            int colL = nt * 8 + q4 * 2;
            stg[colL * 72 + rl] = __float2half(c[nt][0] + bs[colL]);
            stg[(colL + 1) * 72 + rl] = __float2half(c[nt][1] + bs[colL + 1]);
            stg[colL * 72 + rl + 8] = __float2half(c[nt][2] + bs[colL]);
            stg[(colL + 1) * 72 + rl + 8] = __float2half(c[nt][3] + bs[colL + 1]);
        }
        __syncthreads();
        __half* Vt = (__half*)Cout;
        const int bb = m0 >> 11;            // batch
        const int t0 = m0 & (TT - 1);
#pragma unroll
        for (int it = 0; it < 8; it++) {
            int cidx = tid + it * 128;
            int colL = cidx >> 3;           // 0..127
            int tc = (cidx & 7) * 8;
            int n = n0 + colL;
            int hh = n >> 6, d = n & 63;
            uint4 v = *(uint4*)&stg[colL * 72 + tc];
            *(uint4*)&Vt[(size_t)((bb * HH + hh) * DH + d) * TT + t0 + tc] = v;
        }
    } else if (out_half) {
        __half* C = (__half*)Cout;
#pragma unroll
        for (int nt = 0; nt < 16; nt++) {
            int col = n0 + nt * 8 + q4 * 2;
            int bcol = nt * 8 + q4 * 2;
            uint32_t p0 = packh2(c[nt][0] + bs[bcol], c[nt][1] + bs[bcol + 1]);
            uint32_t p1 = packh2(c[nt][2] + bs[bcol], c[nt][3] + bs[bcol + 1]);
            *(uint32_t*)&C[(size_t)r0 * DD + col] = p0;
            *(uint32_t*)&C[(size_t)(r0 + 8) * DD + col] = p1;
        }
    } else {
        float* C = (float*)Cout;
#pragma unroll
        for (int nt = 0; nt < 16; nt++) {
            int col = n0 + nt * 8 + q4 * 2;
            int bcol = nt * 8 + q4 * 2;
            *(float2*)&C[(size_t)r0 * DD + col] =
                make_float2(c[nt][0] + bs[bcol], c[nt][1] + bs[bcol + 1]);
            *(float2*)&C[(size_t)(r0 + 8) * DD + col] =
                make_float2(c[nt][2] + bs[bcol], c[nt][3] + bs[bcol + 1]);
        }
    }
}

// ---------------------------------------------------------------------------
// Attention fp16. Grid (T/128, H, B), 128 threads (4 warps, m32 each).
// ldmatrix.x4 for all K/V B-fragments (conflict-free at pitch 72).
// ---------------------------------------------------------------------------
#define KSP 72                      // halves per row (64 + 8 pad)
#define AKT_H (KT * KSP)            // 4608 halves per K or V tile

__global__ void __launch_bounds__(128) attn_f16_kernel(
    const __half* __restrict__ Q, const __half* __restrict__ K,
    const __half* __restrict__ Vt, const float* __restrict__ rb,
    __half* __restrict__ O)
{
    __shared__ __align__(16) __half ks_[2][AKT_H];
    __shared__ __align__(16) __half vs_[2][AKT_H];
    __shared__ float bias_s[72];
    const uint32_t kb = smem_u32(ks_);
    const uint32_t vb = smem_u32(vs_);

    const int tid = threadIdx.x;
    const int lane = tid & 31;
    const int wid = tid >> 5;        // 0..3
    const int wr = wid * 32;
    const int g = lane >> 2, q4 = lane & 3;
    const int q0 = blockIdx.x * 128;
    const int h = blockIdx.y, b = blockIdx.z;
    const int base = b * TT * DD + h * DH;
    const int vtbase = (b * HH + h) * DH * TT;

    const int lr = tid >> 3;            // 0..15
    const int lc = (tid & 7) * 8;       // halves column (16B chunks)

    // ldmatrix per-lane offset: 4 matrices = (nt even/odd) x (k lo/hi 8)
    const int grp = lane >> 3, lrow = lane & 7;
    const int lmoff = (((grp >> 1) * 8 + lrow) * KSP + (grp & 1) * 8) * 2;   // bytes

    // prologue: stage 0
#pragma unroll
    for (int it = 0; it < 4; it++) {
        int r = lr + it * 16;
        cpasync16(kb + (r * KSP + lc) * 2, &K[base + r * DD + lc]);
        cpasync16(vb + (r * KSP + lc) * 2, &Vt[vtbase + r * TT + lc]);
    }
    CP_COMMIT();

    if (tid < 2 * MAXREL + 1) bias_s[tid] = rb[h * (2 * MAXREL + 1) + tid] * L2E;
    const float blo = rb[h * (2 * MAXREL + 1)] * L2E;
    const float bhi = rb[h * (2 * MAXREL + 1) + 2 * MAXREL] * L2E;

    // Q fragments in registers: 2 slabs x 4 k-steps
    uint32_t qf[2][4][4];
#pragma unroll
    for (int ss = 0; ss < 2; ss++) {
        const int r = q0 + wr + ss * 16 + g;
#pragma unroll
        for (int ksi = 0; ksi < 4; ksi++) {
            const int ac = q4 * 2 + ksi * 16;
            qf[ss][ksi][0] = *(const uint32_t*)&Q[base + r * DD + ac];
            qf[ss][ksi][1] = *(const uint32_t*)&Q[base + (r + 8) * DD + ac];
            qf[ss][ksi][2] = *(const uint32_t*)&Q[base + r * DD + ac + 8];
            qf[ss][ksi][3] = *(const uint32_t*)&Q[base + (r + 8) * DD + ac + 8];
        }
    }

    float o[2][8][4];
#pragma unroll
    for (int ss = 0; ss < 2; ss++)
#pragma unroll
        for (int nt = 0; nt < 8; nt++)
#pragma unroll
            for (int j = 0; j < 4; j++) o[ss][nt][j] = 0.0f;
    float ls[2][2] = {{0.f, 0.f}, {0.f, 0.f}};

    for (int kt = 0; kt < NKT; kt++) {
        const int k0 = kt * KT;
        if (kt + 1 < NKT) {
            const int kn = (kt + 1) * KT;
            const int st = (kt + 1) & 1;
#pragma unroll
            for (int it = 0; it < 4; it++) {
                int r = lr + it * 16;
                cpasync16(kb + (st * AKT_H + r * KSP + lc) * 2, &K[base + (kn + r) * DD + lc]);
                cpasync16(vb + (st * AKT_H + r * KSP + lc) * 2, &Vt[vtbase + r * TT + kn + lc]);
            }
        }
        CP_COMMIT();
        CP_WAIT1();
        __syncthreads();

        const uint32_t kaddr = kb + (kt & 1) * AKT_H * 2 + lmoff;
        const uint32_t vaddr = vb + (kt & 1) * AKT_H * 2 + lmoff;

        // S = Q K^T  (m=32/warp, n=64 keys, k=64 dh)
        float s[2][8][4];
#pragma unroll
        for (int ss = 0; ss < 2; ss++)
#pragma unroll
            for (int nt = 0; nt < 8; nt++)
#pragma unroll
                for (int j = 0; j < 4; j++) s[ss][nt][j] = 0.0f;

#pragma unroll
        for (int ksi = 0; ksi < 4; ksi++) {
#pragma unroll
            for (int ntp = 0; ntp < 4; ntp++) {
                uint32_t b0, b1, b2, b3;
                ldsm4(b0, b1, b2, b3, kaddr + (ntp * 16 * KSP + ksi * 16) * 2);
                mma16(s[0][2 * ntp], qf[0][ksi], b0, b1);
                mma16(s[1][2 * ntp], qf[1][ksi], b0, b1);
                mma16(s[0][2 * ntp + 1], qf[0][ksi], b2, b3);
                mma16(s[1][2 * ntp + 1], qf[1][ksi], b2, b3);
            }
        }

        // softmax weights: p = exp2(s*scale*l2e + bias*l2e)
        const int dmin = q0 - (k0 + KT - 1);
        const int dmax = q0 + 127 - k0;
        if (dmin >= MAXREL) {
#pragma unroll
            for (int ss = 0; ss < 2; ss++)
#pragma unroll
                for (int nt = 0; nt < 8; nt++)
#pragma unroll
                    for (int j = 0; j < 4; j++)
                        s[ss][nt][j] = ex2(fmaf(s[ss][nt][j], SCALE_L2E, bhi));
        } else if (dmax <= -MAXREL) {
#pragma unroll
            for (int ss = 0; ss < 2; ss++)
#pragma unroll
                for (int nt = 0; nt < 8; nt++)
#pragma unroll
                    for (int j = 0; j < 4; j++)
                        s[ss][nt][j] = ex2(fmaf(s[ss][nt][j], SCALE_L2E, blo));
        } else {
#pragma unroll
            for (int ss = 0; ss < 2; ss++) {
                const int dr0 = q0 + wr + ss * 16 + g;
#pragma unroll
                for (int nt = 0; nt < 8; nt++) {
                    const int c0 = k0 + nt * 8 + q4 * 2;
#pragma unroll
                    for (int j = 0; j < 4; j++) {
                        int rel = (dr0 + ((j >> 1) << 3)) - (c0 + (j & 1));
                        rel = min(max(rel, -MAXREL), MAXREL) + MAXREL;
                        s[ss][nt][j] = ex2(fmaf(s[ss][nt][j], SCALE_L2E, bias_s[rel]));
                    }
                }
            }
        }
#pragma unroll
        for (int ss = 0; ss < 2; ss++)
#pragma unroll
            for (int nt = 0; nt < 8; nt++) {
                ls[ss][0] += s[ss][nt][0] + s[ss][nt][1];
                ls[ss][1] += s[ss][nt][2] + s[ss][nt][3];
            }

        // O += P V: pack S C-fragments into PV A-fragments; ldmatrix V B-frags
#pragma unroll
        for (int ksi = 0; ksi < 4; ksi++) {
            uint32_t a0[4], a1[4];
            a0[0] = packh2(s[0][2 * ksi][0], s[0][2 * ksi][1]);
            a0[1] = packh2(s[0][2 * ksi][2], s[0][2 * ksi][3]);
            a0[2] = packh2(s[0][2 * ksi + 1][0], s[0][2 * ksi + 1][1]);
            a0[3] = packh2(s[0][2 * ksi + 1][2], s[0][2 * ksi + 1][3]);
            a1[0] = packh2(s[1][2 * ksi][0], s[1][2 * ksi][1]);
            a1[1] = packh2(s[1][2 * ksi][2], s[1][2 * ksi][3]);
            a1[2] = packh2(s[1][2 * ksi + 1][0], s[1][2 * ksi + 1][1]);
            a1[3] = packh2(s[1][2 * ksi + 1][2], s[1][2 * ksi + 1][3]);
#pragma unroll
            for (int ntp = 0; ntp < 4; ntp++) {
                uint32_t b0, b1, b2, b3;
                ldsm4(b0, b1, b2, b3, vaddr + (ntp * 16 * KSP + ksi * 16) * 2);
                mma16(o[0][2 * ntp], a0, b0, b1);
                mma16(o[1][2 * ntp], a1, b0, b1);
                mma16(o[0][2 * ntp + 1], a0, b2, b3);
                mma16(o[1][2 * ntp + 1], a1, b2, b3);
            }
        }
        __syncthreads();
    }

#pragma unroll
    for (int ss = 0; ss < 2; ss++) {
#pragma unroll
        for (int j = 0; j < 2; j++) {
            ls[ss][j] += __shfl_xor_sync(0xffffffffu, ls[ss][j], 1);
            ls[ss][j] += __shfl_xor_sync(0xffffffffu, ls[ss][j], 2);
        }
        const float inv0 = 1.0f / ls[ss][0];
        const float inv1 = 1.0f / ls[ss][1];
        const int r0 = q0 + wr + ss * 16 + g;
#pragma unroll
        for (int nt = 0; nt < 8; nt++) {
            int col = nt * 8 + q4 * 2;
            uint32_t p0 = packh2(o[ss][nt][0] * inv0, o[ss][nt][1] * inv0);
            uint32_t p1 = packh2(o[ss][nt][2] * inv1, o[ss][nt][3] * inv1);
            *(uint32_t*)&O[base + r0 * DD + col] = p0;
            *(uint32_t*)&O[base + (r0 + 8) * DD + col] = p1;
        }
    }
}

// ---------------------------------------------------------------------------
extern "C" void kernel_launch(void* const* d_in, const int* in_sizes, int n_in,
                              void* d_out, int out_size)
{
    const float* hs = (const float*)d_in[0];
    const float* Wq = (const float*)d_in[1];
    const float* bq = (const float*)d_in[2];
    const float* Wk = (const float*)d_in[3];
    const float* bk = (const float*)d_in[4];
    const float* Wv = (const float*)d_in[5];
    const float* bv = (const float*)d_in[6];
    const float* Wo = (const float*)d_in[7];
    const float* bo = (const float*)d_in[8];
    const float* rb = (const float*)d_in[9];

    __half *pQ, *pK, *pVt, *pAO, *pX, *pW;
    cudaGetSymbolAddress((void**)&pQ, g_Qh);
    cudaGetSymbolAddress((void**)&pK, g_Kh);
    cudaGetSymbolAddress((void**)&pVt, g_Vth);
    cudaGetSymbolAddress((void**)&pAO, g_AOh);
    cudaGetSymbolAddress((void**)&pX, g_Xh);
    cudaGetSymbolAddress((void**)&pW, g_Wth);

    cudaFuncSetAttribute(gemm_f16_kernel,
                         cudaFuncAttributeMaxDynamicSharedMemorySize, GEMM_SMEM_B);

    // prep: z=0..3 weight transpose+cvt, z=4 hidden-state cvt
    prep_kernel<<<dim3(DD / 32, DD / 32, 5), dim3(32, 8)>>>(hs, Wq, Wk, Wv, Wo, pX, pW);

    // Fused Q/K/V projections; z==2 writes V transposed straight into Vt
    gemm_f16_kernel<<<dim3(DD / 128, BB * TT / 64, 3), 128, GEMM_SMEM_B>>>(
        pX, pW, 0, bq, bk, bv, pQ, pK, pVt, 1, 2);

    attn_f16_kernel<<<dim3(TT / 128, HH, BB), 128>>>(pQ, pK, pVt, rb, pAO);

    // Output projection (wbase=3, fp32 out, no transpose)
    gemm_f16_kernel<<<dim3(DD / 128, BB * TT / 64, 1), 128, GEMM_SMEM_B>>>(
        pAO, pW, 3, bo, bo, bo, d_out, d_out, d_out, 0, -1);
}